// round 13
// baseline (speedup 1.0000x reference)
#include <cuda_runtime.h>
#include <cuda_fp16.h>
#include <math.h>
#include <stdint.h>
#include <string.h>

// Problem constants
#define Bb   16
#define Ss   1024
#define Dd   512
#define Hh   8
#define DH   64
#define Ll   6
#define FF   2048
#define ROWS (Bb*Ss)       // 16384
#define KP1  (2*Dd)        // 1024  (fp16 2-term split K' for K=512)
#define KP2  (2*FF)        // 4096  (fp16 2-term split K' for K=2048)

// ---------------- scratch (device globals; no runtime allocation) -------------
__device__ float g_x[ROWS*Dd];
__device__ float g_q[ROWS*Dd];
__device__ float g_k[ROWS*Dd];
__device__ float g_v[ROWS*Dd];
__device__ float g_attn[ROWS*Dd];
__device__ float g_proj[ROWS*Dd];
__device__ float g_h[ROWS*FF];
__device__ __half g_xb[(size_t)ROWS*KP1];   // 32 MB  split-fp16 activations
__device__ __half g_hb[(size_t)ROWS*KP2];   // 128 MB split-fp16 FFN hidden
__device__ __half g_wb[(size_t)FF*KP1];     // 4 MB   split-fp16 weight staging

// ======================= PTX helpers (portable, sm_80+) =======================
__device__ __forceinline__ uint32_t smem_u32(const void* p) {
    uint32_t a;
    asm("{ .reg .u64 t; cvta.to.shared.u64 t, %1; cvt.u32.u64 %0, t; }" : "=r"(a) : "l"(p));
    return a;
}
#define CP_ASYNC16(dst, src) \
    asm volatile("cp.async.cg.shared.global [%0], [%1], 16;" :: "r"(dst), "l"(src) : "memory")
#define CP_COMMIT() asm volatile("cp.async.commit_group;" ::: "memory")
#define CP_WAIT(n)  asm volatile("cp.async.wait_group %0;" :: "n"(n) : "memory")

#define SWZ128(o) ((o) ^ (((o) >> 3) & 0x70))

__device__ __forceinline__ void ldmatrix_x4(uint32_t& r0, uint32_t& r1, uint32_t& r2, uint32_t& r3,
                                            uint32_t addr) {
    asm volatile("ldmatrix.sync.aligned.m8n8.x4.shared.b16 {%0,%1,%2,%3}, [%4];"
                 : "=r"(r0), "=r"(r1), "=r"(r2), "=r"(r3) : "r"(addr));
}
// fp16 inputs, fp32 accumulate
__device__ __forceinline__ void mma_16816(float& c0, float& c1, float& c2, float& c3,
                                          uint32_t a0, uint32_t a1, uint32_t a2, uint32_t a3,
                                          uint32_t b0, uint32_t b1) {
    asm volatile("mma.sync.aligned.m16n8k16.row.col.f32.f16.f16.f32 "
                 "{%0,%1,%2,%3}, {%4,%5,%6,%7}, {%8,%9}, {%10,%11,%12,%13};"
                 : "=f"(c0), "=f"(c1), "=f"(c2), "=f"(c3)
                 : "r"(a0), "r"(a1), "r"(a2), "r"(a3), "r"(b0), "r"(b1),
                   "f"(c0), "f"(c1), "f"(c2), "f"(c3));
}

// ================= split-fp16 conversion kernels ==============================
// src [R,K] fp32 -> dst [R,2K] fp16 blocks.
// AMODE (activations): [hi | lo]  (A represented exactly: hi+lo = A)
// !AMODE (weights):    [hi | hi]  (product = A_exact * W_hi)
template <bool AMODE>
__global__ void conv_split(const float* __restrict__ src, __half* __restrict__ dst, int K) {
    size_t lin = ((size_t)blockIdx.x * 256 + threadIdx.x) * 4;
    int r = (int)(lin / K);
    int k = (int)(lin % K);
    float4 v = *(const float4*)(src + lin);
    float vv[4] = {v.x, v.y, v.z, v.w};
    __half h[4], lo[4];
    #pragma unroll
    for (int i = 0; i < 4; i++) {
        h[i]  = __float2half(vv[i]);
        lo[i] = __float2half(vv[i] - __half2float(h[i]));
    }
    size_t base = (size_t)r * (2 * (size_t)K) + k;
    uint32_t hp0, hp1, lp0, lp1;
    {
        __half2 a = __halves2half2(h[0], h[1]), b = __halves2half2(h[2], h[3]);
        __half2 c = __halves2half2(lo[0], lo[1]), d = __halves2half2(lo[2], lo[3]);
        memcpy(&hp0, &a, 4); memcpy(&hp1, &b, 4); memcpy(&lp0, &c, 4); memcpy(&lp1, &d, 4);
    }
    uint2 hv = make_uint2(hp0, hp1);
    uint2 lv = make_uint2(lp0, lp1);
    *(uint2*)(dst + base)     = hv;
    *(uint2*)(dst + base + K) = AMODE ? lv : hv;
}

// ================= HMMA GEMM: C[M,N] = A'[M,Kp] @ W'[N,Kp]^T + bias ===========
// 128x128 CTA tile, BK=64, 256 threads (8 warps 2x4), mma.sync m16n8k16 fp16,
// SW128-swizzled smem, 3-stage cp.async pipeline (prefetch distance 2).
#define GEMM_SMEM_BYTES (6 * 16384)   // 96 KB: 3 stages x (16K A + 16K B)
template <bool RELU>
__global__ void __launch_bounds__(256, 2) gemm_hmma(
    const __half* __restrict__ A, const __half* __restrict__ W,
    const float* __restrict__ bias, float* __restrict__ C, int M, int N, int Kp) {
    extern __shared__ char smem[];
    const uint32_t sb = smem_u32(smem);
    const int tid = threadIdx.x;
    const int lane = tid & 31, wid = tid >> 5;
    const int wm = wid & 1, wn = wid >> 1;
    const int m0 = blockIdx.y * 128, n0 = blockIdx.x * 128;

    const uint32_t offA[3] = {0u, 32768u, 65536u};
    const uint32_t offB[3] = {16384u, 49152u, 81920u};

    const __half* Ap = A + (size_t)m0 * Kp;
    const __half* Bp = W + (size_t)n0 * Kp;
    const int nc = Kp >> 6;

    const int lrow = tid >> 1;
    const int lch0 = (tid & 1) * 4;

    float acc[4][4][4];
    #pragma unroll
    for (int i = 0; i < 4; i++)
        #pragma unroll
        for (int j = 0; j < 4; j++)
            #pragma unroll
            for (int r = 0; r < 4; r++) acc[i][j][r] = 0.f;

    auto issue = [&](int i, int s) {
        const __half* Ac = Ap + (size_t)i * 64;
        const __half* Bc = Bp + (size_t)i * 64;
        #pragma unroll
        for (int j = 0; j < 4; j++) {
            int ch = lch0 + j;
            uint32_t so = SWZ128((uint32_t)(lrow * 128 + ch * 16));
            CP_ASYNC16(sb + offA[s] + so, Ac + (size_t)lrow * Kp + ch * 8);
            CP_ASYNC16(sb + offB[s] + so, Bc + (size_t)lrow * Kp + ch * 8);
        }
    };

    // prologue: prime two stages
    issue(0, 0); CP_COMMIT();
    issue(1, 1); CP_COMMIT();

    int b = 0;
    for (int i = 0; i < nc; i++) {
        if (i + 2 < nc) {
            int s = b + 2; if (s >= 3) s -= 3;
            issue(i + 2, s); CP_COMMIT();
            CP_WAIT(2);
        } else if (i + 1 < nc) {
            CP_WAIT(1);
        } else {
            CP_WAIT(0);
        }
        __syncthreads();

        const uint32_t baA = sb + offA[b];
        const uint32_t baB = sb + offB[b];
        #pragma unroll
        for (int kk = 0; kk < 4; kk++) {
            uint32_t a[4][4];
            {
                int r = lane & 15, half = lane >> 4;
                #pragma unroll
                for (int mi = 0; mi < 4; mi++) {
                    int row = wm * 64 + mi * 16 + r;
                    uint32_t off = (uint32_t)(row * 128)
                                 + (uint32_t)((kk * 32 + half * 16) ^ ((row & 7) * 16));
                    ldmatrix_x4(a[mi][0], a[mi][1], a[mi][2], a[mi][3], baA + off);
                }
            }
            uint32_t bfr[4][2];
            {
                int g = lane >> 3, r8 = lane & 7;
                #pragma unroll
                for (int p = 0; p < 2; p++) {
                    int row = wn * 32 + p * 16 + (g & 1) * 8 + r8;
                    uint32_t off = (uint32_t)(row * 128)
                                 + (uint32_t)((kk * 32 + (g >> 1) * 16) ^ ((row & 7) * 16));
                    uint32_t r0, r1, r2, r3;
                    ldmatrix_x4(r0, r1, r2, r3, baB + off);
                    bfr[p * 2 + 0][0] = r0; bfr[p * 2 + 0][1] = r2;
                    bfr[p * 2 + 1][0] = r1; bfr[p * 2 + 1][1] = r3;
                }
            }
            #pragma unroll
            for (int mi = 0; mi < 4; mi++)
                #pragma unroll
                for (int ni = 0; ni < 4; ni++)
                    mma_16816(acc[mi][ni][0], acc[mi][ni][1], acc[mi][ni][2], acc[mi][ni][3],
                              a[mi][0], a[mi][1], a[mi][2], a[mi][3],
                              bfr[ni][0], bfr[ni][1]);
        }
        __syncthreads();
        if (++b == 3) b = 0;
    }

    #pragma unroll
    for (int mi = 0; mi < 4; mi++) {
        int row0 = m0 + wm * 64 + mi * 16 + (lane >> 2);
        #pragma unroll
        for (int ni = 0; ni < 4; ni++) {
            int col = n0 + wn * 32 + ni * 8 + (lane & 3) * 2;
            float b0 = bias[col], b1 = bias[col + 1];
            float2 v0 = make_float2(acc[mi][ni][0] + b0, acc[mi][ni][1] + b1);
            float2 v1 = make_float2(acc[mi][ni][2] + b0, acc[mi][ni][3] + b1);
            if (RELU) {
                v0.x = fmaxf(v0.x, 0.f); v0.y = fmaxf(v0.y, 0.f);
                v1.x = fmaxf(v1.x, 0.f); v1.y = fmaxf(v1.y, 0.f);
            }
            *(float2*)(C + (size_t)row0 * N + col)       = v0;
            *(float2*)(C + (size_t)(row0 + 8) * N + col) = v1;
        }
    }
}

// ---------------- embedding + positional + mask -------------------------------
__global__ void embed_kernel(const int* __restrict__ inp, const int* __restrict__ mask,
                             const float* __restrict__ emb, const float* __restrict__ pos) {
    int row = blockIdx.x;
    int tok = inp[row];
    float mf = (float)mask[row];
    int s = row & (Ss - 1);
    const float* er = emb + (size_t)tok * Dd;
    const float* pr = pos + (size_t)s * Dd;
    float* xr = g_x + (size_t)row * Dd;
    for (int d = threadIdx.x; d < Dd; d += blockDim.x)
        xr[d] = (er[d] + pr[d]) * mf;
}

// ---------------- fused flash attention (fp32, validated) ---------------------
#define ATTN_SMEM_FLOATS (4*64*65 + 128)
__global__ void attn_kernel(const float* __restrict__ q, const float* __restrict__ k,
                            const float* __restrict__ v, const int* __restrict__ mask,
                            float* __restrict__ out) {
    extern __shared__ float sm[];
    float* sQ = sm;
    float* sK = sQ + 64 * 65;
    float* sV = sK + 64 * 65;
    float* sS = sV + 64 * 65;
    float* sScale = sS + 64 * 65;
    float* sL = sScale + 64;

    int bh = blockIdx.y;
    int b = bh >> 3, h = bh & 7;
    int q0 = blockIdx.x * 64;
    int tid = threadIdx.x;
    int tx = tid & 15, ty = tid >> 4;
    size_t base = ((size_t)b * Ss) * Dd + h * DH;

    {
        int c = tid & 63, r0 = tid >> 6;
        for (int r = r0; r < 64; r += 4)
            sQ[r * 65 + c] = q[base + (size_t)(q0 + r) * Dd + c];
    }

    float oacc[4][4] = {};
    float m_i = -INFINITY, l_i = 0.f;

    for (int k0 = 0; k0 < Ss; k0 += 64) {
        {
            int c = tid & 63, r0 = tid >> 6;
            for (int r = r0; r < 64; r += 4) {
                sK[r * 65 + c] = k[base + (size_t)(k0 + r) * Dd + c];
                sV[r * 65 + c] = v[base + (size_t)(k0 + r) * Dd + c];
            }
        }
        __syncthreads();

        float acc[4][4] = {};
        #pragma unroll
        for (int kk = 0; kk < 64; kk++) {
            float ra[4], rb[4];
            #pragma unroll
            for (int i = 0; i < 4; i++) ra[i] = sQ[(ty * 4 + i) * 65 + kk];
            #pragma unroll
            for (int j = 0; j < 4; j++) rb[j] = sK[(tx * 4 + j) * 65 + kk];
            #pragma unroll
            for (int i = 0; i < 4; i++)
                #pragma unroll
                for (int j = 0; j < 4; j++)
                    acc[i][j] += ra[i] * rb[j];
        }
        #pragma unroll
        for (int j = 0; j < 4; j++) {
            int c = tx * 4 + j;
            bool keep = mask[b * Ss + k0 + c] != 0;
            #pragma unroll
            for (int i = 0; i < 4; i++) {
                float vv = keep ? acc[i][j] : -1e20f;
                sS[(ty * 4 + i) * 65 + c] = vv * 0.125f;
            }
        }
        __syncthreads();

        if (tid < 64) {
            int r = tid;
            float tm = -INFINITY;
            #pragma unroll 8
            for (int c = 0; c < 64; c++) tm = fmaxf(tm, sS[r * 65 + c]);
            float mn = fmaxf(m_i, tm);
            float ps = 0.f;
            #pragma unroll 8
            for (int c = 0; c < 64; c++) {
                float p = __expf(sS[r * 65 + c] - mn);
                sS[r * 65 + c] = p;
                ps += p;
            }
            float sc = (m_i == -INFINITY) ? 0.f : __expf(m_i - mn);
            l_i = l_i * sc + ps;
            m_i = mn;
            sScale[r] = sc;
        }
        __syncthreads();

        #pragma unroll
        for (int i = 0; i < 4; i++) {
            float sc = sScale[ty * 4 + i];
            #pragma unroll
            for (int j = 0; j < 4; j++) oacc[i][j] *= sc;
        }
        #pragma unroll
        for (int kk = 0; kk < 64; kk++) {
            float rp[4], rv[4];
            #pragma unroll
            for (int i = 0; i < 4; i++) rp[i] = sS[(ty * 4 + i) * 65 + kk];
            #pragma unroll
            for (int j = 0; j < 4; j++) rv[j] = sV[kk * 65 + tx * 4 + j];
            #pragma unroll
            for (int i = 0; i < 4; i++)
                #pragma unroll
                for (int j = 0; j < 4; j++)
                    oacc[i][j] += rp[i] * rv[j];
        }
        __syncthreads();
    }

    if (tid < 64) sL[tid] = l_i;
    __syncthreads();
    #pragma unroll
    for (int i = 0; i < 4; i++) {
        int r = ty * 4 + i;
        float inv = 1.f / sL[r];
        #pragma unroll
        for (int j = 0; j < 4; j++)
            out[base + (size_t)(q0 + r) * Dd + tx * 4 + j] = oacc[i][j] * inv;
    }
}

// ---------------- residual add + LayerNorm (+optional mask mult) --------------
__global__ void ln_residual_kernel(const float* __restrict__ xin, const float* __restrict__ res,
                                   const float* __restrict__ g, const float* __restrict__ beta,
                                   float* __restrict__ outp, const int* __restrict__ mask) {
    __shared__ float red[8];
    int row = blockIdx.x, tid = threadIdx.x;
    const float* xr = xin + (size_t)row * Dd;
    const float* rr = res + (size_t)row * Dd;
    float v0 = xr[tid] + rr[tid];
    float v1 = xr[tid + 256] + rr[tid + 256];

    float s = v0 + v1;
    #pragma unroll
    for (int o = 16; o > 0; o >>= 1) s += __shfl_down_sync(0xffffffffu, s, o);
    if ((tid & 31) == 0) red[tid >> 5] = s;
    __syncthreads();
    if (tid < 8) {
        float t = red[tid];
        #pragma unroll
        for (int o = 4; o > 0; o >>= 1) t += __shfl_down_sync(0xffu, t, o);
        if (tid == 0) red[0] = t;
    }
    __syncthreads();
    float mean = red[0] * (1.f / Dd);
    __syncthreads();

    float d0 = v0 - mean, d1 = v1 - mean;
    float vs = d0 * d0 + d1 * d1;
    #pragma unroll
    for (int o = 16; o > 0; o >>= 1) vs += __shfl_down_sync(0xffffffffu, vs, o);
    if ((tid & 31) == 0) red[tid >> 5] = vs;
    __syncthreads();
    if (tid < 8) {
        float t = red[tid];
        #pragma unroll
        for (int o = 4; o > 0; o >>= 1) t += __shfl_down_sync(0xffu, t, o);
        if (tid == 0) red[0] = t;
    }
    __syncthreads();
    float var = red[0] * (1.f / Dd);
    float inv = rsqrtf(var + 1e-5f);
    float mf = mask ? (float)mask[row] : 1.f;
    outp[(size_t)row * Dd + tid]       = (d0 * inv * g[tid]       + beta[tid])       * mf;
    outp[(size_t)row * Dd + tid + 256] = (d1 * inv * g[tid + 256] + beta[tid + 256]) * mf;
}

// ---------------- masked mean pool over sequence ------------------------------
__global__ void pool_kernel(const int* __restrict__ mask, float* __restrict__ out) {
    __shared__ float red[8];
    int b = blockIdx.x, tid = threadIdx.x;
    float s0 = 0.f, s1 = 0.f;
    for (int t = 0; t < Ss; t++) {
        const float* xr = g_x + ((size_t)(b * Ss + t)) * Dd;
        s0 += xr[tid];
        s1 += xr[tid + 256];
    }
    float c = 0.f;
    for (int t = tid; t < Ss; t += 256) c += (float)mask[b * Ss + t];
    #pragma unroll
    for (int o = 16; o > 0; o >>= 1) c += __shfl_down_sync(0xffffffffu, c, o);
    if ((tid & 31) == 0) red[tid >> 5] = c;
    __syncthreads();
    if (tid < 8) {
        float t2 = red[tid];
        #pragma unroll
        for (int o = 4; o > 0; o >>= 1) t2 += __shfl_down_sync(0xffu, t2, o);
        if (tid == 0) red[0] = t2;
    }
    __syncthreads();
    float div = fmaxf(red[0], 1e-20f);
    out[b * Dd + tid]       = s0 / div;
    out[b * Dd + tid + 256] = s1 / div;
}

// ---------------- host orchestration ------------------------------------------
extern "C" void kernel_launch(void* const* d_in, const int* in_sizes, int n_in,
                              void* d_out, int out_size) {
    (void)in_sizes; (void)n_in; (void)out_size;
    const int*   inp   = (const int*)  d_in[0];
    const int*   mask  = (const int*)  d_in[1];
    const float* emb   = (const float*)d_in[2];
    const float* pos   = (const float*)d_in[3];
    const float* Wq    = (const float*)d_in[4];
    const float* bq    = (const float*)d_in[5];
    const float* Wk    = (const float*)d_in[6];
    const float* bk    = (const float*)d_in[7];
    const float* Wv    = (const float*)d_in[8];
    const float* bv    = (const float*)d_in[9];
    const float* Wo    = (const float*)d_in[10];
    const float* bo    = (const float*)d_in[11];
    const float* ln1g  = (const float*)d_in[12];
    const float* ln1b  = (const float*)d_in[13];
    const float* W1    = (const float*)d_in[14];
    const float* b1    = (const float*)d_in[15];
    const float* W2    = (const float*)d_in[16];
    const float* b2    = (const float*)d_in[17];
    const float* ln2g  = (const float*)d_in[18];
    const float* ln2b  = (const float*)d_in[19];
    float* out = (float*)d_out;

    float *xp, *qp, *kp, *vp, *ap, *pp, *hp;
    __half *xb, *hb, *wb;
    cudaGetSymbolAddress((void**)&xp, g_x);
    cudaGetSymbolAddress((void**)&qp, g_q);
    cudaGetSymbolAddress((void**)&kp, g_k);
    cudaGetSymbolAddress((void**)&vp, g_v);
    cudaGetSymbolAddress((void**)&ap, g_attn);
    cudaGetSymbolAddress((void**)&pp, g_proj);
    cudaGetSymbolAddress((void**)&hp, g_h);
    cudaGetSymbolAddress((void**)&xb, g_xb);
    cudaGetSymbolAddress((void**)&hb, g_hb);
    cudaGetSymbolAddress((void**)&wb, g_wb);

    const int attn_smem = ATTN_SMEM_FLOATS * (int)sizeof(float);
    cudaFuncSetAttribute(attn_kernel, cudaFuncAttributeMaxDynamicSharedMemorySize, attn_smem);
    cudaFuncSetAttribute(gemm_hmma<false>, cudaFuncAttributeMaxDynamicSharedMemorySize, GEMM_SMEM_BYTES);
    cudaFuncSetAttribute(gemm_hmma<true>,  cudaFuncAttributeMaxDynamicSharedMemorySize, GEMM_SMEM_BYTES);

    embed_kernel<<<ROWS, 256>>>(inp, mask, emb, pos);

    dim3 gD(Dd / 128, ROWS / 128);
    dim3 gF(FF / 128, ROWS / 128);
    dim3 gA(Ss / 64, Bb * Hh);

    const int cvActD = (ROWS * Dd) / 1024;
    const int cvActF = (ROWS * FF) / 1024;
    const int cvWdd  = (Dd * Dd) / 1024;
    const int cvW1   = (FF * Dd) / 1024;
    const int cvW2   = (Dd * FF) / 1024;

    for (int l = 0; l < Ll; l++) {
        const float* Wq_l = Wq + (size_t)l * Dd * Dd;
        const float* Wk_l = Wk + (size_t)l * Dd * Dd;
        const float* Wv_l = Wv + (size_t)l * Dd * Dd;
        const float* Wo_l = Wo + (size_t)l * Dd * Dd;
        const float* W1_l = W1 + (size_t)l * FF * Dd;
        const float* W2_l = W2 + (size_t)l * Dd * FF;
        const float* bq_l = bq + (size_t)l * Dd;
        const float* bk_l = bk + (size_t)l * Dd;
        const float* bv_l = bv + (size_t)l * Dd;
        const float* bo_l = bo + (size_t)l * Dd;
        const float* b1_l = b1 + (size_t)l * FF;
        const float* b2_l = b2 + (size_t)l * Dd;

        conv_split<true><<<cvActD, 256>>>(xp, xb, Dd);
        conv_split<false><<<cvWdd, 256>>>(Wq_l, wb, Dd);
        gemm_hmma<false><<<gD, 256, GEMM_SMEM_BYTES>>>(xb, wb, bq_l, qp, ROWS, Dd, KP1);
        conv_split<false><<<cvWdd, 256>>>(Wk_l, wb, Dd);
        gemm_hmma<false><<<gD, 256, GEMM_SMEM_BYTES>>>(xb, wb, bk_l, kp, ROWS, Dd, KP1);
        conv_split<false><<<cvWdd, 256>>>(Wv_l, wb, Dd);
        gemm_hmma<false><<<gD, 256, GEMM_SMEM_BYTES>>>(xb, wb, bv_l, vp, ROWS, Dd, KP1);

        attn_kernel<<<gA, 256, attn_smem>>>(qp, kp, vp, mask, ap);

        conv_split<true><<<cvActD, 256>>>(ap, xb, Dd);
        conv_split<false><<<cvWdd, 256>>>(Wo_l, wb, Dd);
        gemm_hmma<false><<<gD, 256, GEMM_SMEM_BYTES>>>(xb, wb, bo_l, pp, ROWS, Dd, KP1);
        ln_residual_kernel<<<ROWS, 256>>>(xp, pp, ln1g + (size_t)l * Dd, ln1b + (size_t)l * Dd,
                                          xp, (const int*)nullptr);

        conv_split<true><<<cvActD, 256>>>(xp, xb, Dd);
        conv_split<false><<<cvW1, 256>>>(W1_l, wb, Dd);
        gemm_hmma<true><<<gF, 256, GEMM_SMEM_BYTES>>>(xb, wb, b1_l, hp, ROWS, FF, KP1);
        conv_split<true><<<cvActF, 256>>>(hp, hb, FF);
        conv_split<false><<<cvW2, 256>>>(W2_l, wb, FF);
        gemm_hmma<false><<<gD, 256, GEMM_SMEM_BYTES>>>(hb, wb, b2_l, pp, ROWS, Dd, KP2);
        ln_residual_kernel<<<ROWS, 256>>>(xp, pp, ln2g + (size_t)l * Dd, ln2b + (size_t)l * Dd,
                                          xp, mask);
    }

    pool_kernel<<<Bb, 256>>>(mask, out);
}

// round 14
// speedup vs baseline: 1.5697x; 1.5697x over previous
#include <cuda_runtime.h>
#include <cuda_fp16.h>
#include <math.h>
#include <stdint.h>
#include <string.h>

// Problem constants
#define Bb   16
#define Ss   1024
#define Dd   512
#define Hh   8
#define DH   64
#define Ll   6
#define FF   2048
#define ROWS (Bb*Ss)       // 16384
#define KP1  (2*Dd)        // 1024  (fp16 2-term split K' for K=512)
#define KP2  (2*FF)        // 4096  (fp16 2-term split K' for K=2048)

// ---------------- scratch (device globals; no runtime allocation) -------------
__device__ float g_x[ROWS*Dd];
__device__ float g_q[ROWS*Dd];
__device__ float g_k[ROWS*Dd];
__device__ float g_v[ROWS*Dd];
__device__ float g_attn[ROWS*Dd];
__device__ float g_proj[ROWS*Dd];
__device__ float g_h[ROWS*FF];
__device__ __half g_xb[(size_t)ROWS*KP1];   // 32 MB  split-fp16 activations
__device__ __half g_hb[(size_t)ROWS*KP2];   // 128 MB split-fp16 FFN hidden
__device__ __half g_wb[(size_t)FF*KP1];     // 4 MB   split-fp16 weight staging

// ======================= PTX helpers (portable, sm_80+) =======================
__device__ __forceinline__ uint32_t smem_u32(const void* p) {
    uint32_t a;
    asm("{ .reg .u64 t; cvta.to.shared.u64 t, %1; cvt.u32.u64 %0, t; }" : "=r"(a) : "l"(p));
    return a;
}
#define CP_ASYNC16(dst, src) \
    asm volatile("cp.async.cg.shared.global [%0], [%1], 16;" :: "r"(dst), "l"(src) : "memory")
#define CP_COMMIT() asm volatile("cp.async.commit_group;" ::: "memory")
#define CP_WAIT(n)  asm volatile("cp.async.wait_group %0;" :: "n"(n) : "memory")

#define SWZ128(o) ((o) ^ (((o) >> 3) & 0x70))

__device__ __forceinline__ void ldmatrix_x4(uint32_t& r0, uint32_t& r1, uint32_t& r2, uint32_t& r3,
                                            uint32_t addr) {
    asm volatile("ldmatrix.sync.aligned.m8n8.x4.shared.b16 {%0,%1,%2,%3}, [%4];"
                 : "=r"(r0), "=r"(r1), "=r"(r2), "=r"(r3) : "r"(addr));
}
// fp16 inputs, fp32 accumulate
__device__ __forceinline__ void mma_16816(float& c0, float& c1, float& c2, float& c3,
                                          uint32_t a0, uint32_t a1, uint32_t a2, uint32_t a3,
                                          uint32_t b0, uint32_t b1) {
    asm volatile("mma.sync.aligned.m16n8k16.row.col.f32.f16.f16.f32 "
                 "{%0,%1,%2,%3}, {%4,%5,%6,%7}, {%8,%9}, {%10,%11,%12,%13};"
                 : "=f"(c0), "=f"(c1), "=f"(c2), "=f"(c3)
                 : "r"(a0), "r"(a1), "r"(a2), "r"(a3), "r"(b0), "r"(b1),
                   "f"(c0), "f"(c1), "f"(c2), "f"(c3));
}

// ================= split-fp16 conversion kernels ==============================
// src [R,K] fp32 -> dst [R,2K] fp16 blocks.
// AMODE (activations): [hi | lo]  (A represented exactly: hi+lo = A)
// !AMODE (weights):    [hi | hi]  (product = A_exact * W_hi)
template <bool AMODE>
__global__ void conv_split(const float* __restrict__ src, __half* __restrict__ dst, int K) {
    size_t lin = ((size_t)blockIdx.x * 256 + threadIdx.x) * 4;
    int r = (int)(lin / K);
    int k = (int)(lin % K);
    float4 v = *(const float4*)(src + lin);
    float vv[4] = {v.x, v.y, v.z, v.w};
    __half h[4], lo[4];
    #pragma unroll
    for (int i = 0; i < 4; i++) {
        h[i]  = __float2half(vv[i]);
        lo[i] = __float2half(vv[i] - __half2float(h[i]));
    }
    size_t base = (size_t)r * (2 * (size_t)K) + k;
    uint32_t hp0, hp1, lp0, lp1;
    {
        __half2 a = __halves2half2(h[0], h[1]), b = __halves2half2(h[2], h[3]);
        __half2 c = __halves2half2(lo[0], lo[1]), d = __halves2half2(lo[2], lo[3]);
        memcpy(&hp0, &a, 4); memcpy(&hp1, &b, 4); memcpy(&lp0, &c, 4); memcpy(&lp1, &d, 4);
    }
    uint2 hv = make_uint2(hp0, hp1);
    uint2 lv = make_uint2(lp0, lp1);
    *(uint2*)(dst + base)     = hv;
    *(uint2*)(dst + base + K) = AMODE ? lv : hv;
}

// ================= HMMA GEMM: C[M,N] = A'[M,Kp] @ W'[N,Kp]^T + bias ===========
// 128x128 CTA tile, BK=64, 256 threads (8 warps 2x4), mma.sync m16n8k16 fp16,
// SW128-swizzled smem, cp.async double buffering. (R12 champion configuration.)
#define GEMM_SMEM_BYTES (4 * 16384)
template <bool RELU>
__global__ void __launch_bounds__(256, 2) gemm_hmma(
    const __half* __restrict__ A, const __half* __restrict__ W,
    const float* __restrict__ bias, float* __restrict__ C, int M, int N, int Kp) {
    extern __shared__ char smem[];
    const uint32_t sb = smem_u32(smem);
    const int tid = threadIdx.x;
    const int lane = tid & 31, wid = tid >> 5;
    const int wm = wid & 1, wn = wid >> 1;
    const int m0 = blockIdx.y * 128, n0 = blockIdx.x * 128;

    const uint32_t offA[2] = {0u, 32768u};
    const uint32_t offB[2] = {16384u, 49152u};

    const __half* Ap = A + (size_t)m0 * Kp;
    const __half* Bp = W + (size_t)n0 * Kp;
    const int nc = Kp >> 6;

    const int lrow = tid >> 1;
    const int lch0 = (tid & 1) * 4;

    float acc[4][4][4];
    #pragma unroll
    for (int i = 0; i < 4; i++)
        #pragma unroll
        for (int j = 0; j < 4; j++)
            #pragma unroll
            for (int r = 0; r < 4; r++) acc[i][j][r] = 0.f;

    auto issue = [&](int i, int b) {
        const __half* Ac = Ap + (size_t)i * 64;
        const __half* Bc = Bp + (size_t)i * 64;
        #pragma unroll
        for (int j = 0; j < 4; j++) {
            int ch = lch0 + j;
            uint32_t so = SWZ128((uint32_t)(lrow * 128 + ch * 16));
            CP_ASYNC16(sb + offA[b] + so, Ac + (size_t)lrow * Kp + ch * 8);
            CP_ASYNC16(sb + offB[b] + so, Bc + (size_t)lrow * Kp + ch * 8);
        }
    };

    issue(0, 0); CP_COMMIT();

    for (int i = 0; i < nc; i++) {
        int b = i & 1;
        if (i + 1 < nc) { issue(i + 1, b ^ 1); CP_COMMIT(); CP_WAIT(1); }
        else            { CP_WAIT(0); }
        __syncthreads();

        const uint32_t baA = sb + offA[b];
        const uint32_t baB = sb + offB[b];
        #pragma unroll
        for (int kk = 0; kk < 4; kk++) {
            uint32_t a[4][4];
            {
                int r = lane & 15, half = lane >> 4;
                #pragma unroll
                for (int mi = 0; mi < 4; mi++) {
                    int row = wm * 64 + mi * 16 + r;
                    uint32_t off = (uint32_t)(row * 128)
                                 + (uint32_t)((kk * 32 + half * 16) ^ ((row & 7) * 16));
                    ldmatrix_x4(a[mi][0], a[mi][1], a[mi][2], a[mi][3], baA + off);
                }
            }
            uint32_t bfr[4][2];
            {
                int g = lane >> 3, r8 = lane & 7;
                #pragma unroll
                for (int p = 0; p < 2; p++) {
                    int row = wn * 32 + p * 16 + (g & 1) * 8 + r8;
                    uint32_t off = (uint32_t)(row * 128)
                                 + (uint32_t)((kk * 32 + (g >> 1) * 16) ^ ((row & 7) * 16));
                    uint32_t r0, r1, r2, r3;
                    ldmatrix_x4(r0, r1, r2, r3, baB + off);
                    bfr[p * 2 + 0][0] = r0; bfr[p * 2 + 0][1] = r2;
                    bfr[p * 2 + 1][0] = r1; bfr[p * 2 + 1][1] = r3;
                }
            }
            #pragma unroll
            for (int mi = 0; mi < 4; mi++)
                #pragma unroll
                for (int ni = 0; ni < 4; ni++)
                    mma_16816(acc[mi][ni][0], acc[mi][ni][1], acc[mi][ni][2], acc[mi][ni][3],
                              a[mi][0], a[mi][1], a[mi][2], a[mi][3],
                              bfr[ni][0], bfr[ni][1]);
        }
        __syncthreads();
    }

    #pragma unroll
    for (int mi = 0; mi < 4; mi++) {
        int row0 = m0 + wm * 64 + mi * 16 + (lane >> 2);
        #pragma unroll
        for (int ni = 0; ni < 4; ni++) {
            int col = n0 + wn * 32 + ni * 8 + (lane & 3) * 2;
            float b0 = bias[col], b1 = bias[col + 1];
            float2 v0 = make_float2(acc[mi][ni][0] + b0, acc[mi][ni][1] + b1);
            float2 v1 = make_float2(acc[mi][ni][2] + b0, acc[mi][ni][3] + b1);
            if (RELU) {
                v0.x = fmaxf(v0.x, 0.f); v0.y = fmaxf(v0.y, 0.f);
                v1.x = fmaxf(v1.x, 0.f); v1.y = fmaxf(v1.y, 0.f);
            }
            *(float2*)(C + (size_t)row0 * N + col)       = v0;
            *(float2*)(C + (size_t)(row0 + 8) * N + col) = v1;
        }
    }
}

// ---------------- embedding + positional + mask -------------------------------
__global__ void embed_kernel(const int* __restrict__ inp, const int* __restrict__ mask,
                             const float* __restrict__ emb, const float* __restrict__ pos) {
    int row = blockIdx.x;
    int tok = inp[row];
    float mf = (float)mask[row];
    int s = row & (Ss - 1);
    const float* er = emb + (size_t)tok * Dd;
    const float* pr = pos + (size_t)s * Dd;
    float* xr = g_x + (size_t)row * Dd;
    for (int d = threadIdx.x; d < Dd; d += blockDim.x)
        xr[d] = (er[d] + pr[d]) * mf;
}

// ---------------- fused flash attention (fp32, validated) ---------------------
#define ATTN_SMEM_FLOATS (4*64*65 + 128)
__global__ void attn_kernel(const float* __restrict__ q, const float* __restrict__ k,
                            const float* __restrict__ v, const int* __restrict__ mask,
                            float* __restrict__ out) {
    extern __shared__ float sm[];
    float* sQ = sm;
    float* sK = sQ + 64 * 65;
    float* sV = sK + 64 * 65;
    float* sS = sV + 64 * 65;
    float* sScale = sS + 64 * 65;
    float* sL = sScale + 64;

    int bh = blockIdx.y;
    int b = bh >> 3, h = bh & 7;
    int q0 = blockIdx.x * 64;
    int tid = threadIdx.x;
    int tx = tid & 15, ty = tid >> 4;
    size_t base = ((size_t)b * Ss) * Dd + h * DH;

    {
        int c = tid & 63, r0 = tid >> 6;
        for (int r = r0; r < 64; r += 4)
            sQ[r * 65 + c] = q[base + (size_t)(q0 + r) * Dd + c];
    }

    float oacc[4][4] = {};
    float m_i = -INFINITY, l_i = 0.f;

    for (int k0 = 0; k0 < Ss; k0 += 64) {
        {
            int c = tid & 63, r0 = tid >> 6;
            for (int r = r0; r < 64; r += 4) {
                sK[r * 65 + c] = k[base + (size_t)(k0 + r) * Dd + c];
                sV[r * 65 + c] = v[base + (size_t)(k0 + r) * Dd + c];
            }
        }
        __syncthreads();

        float acc[4][4] = {};
        #pragma unroll
        for (int kk = 0; kk < 64; kk++) {
            float ra[4], rb[4];
            #pragma unroll
            for (int i = 0; i < 4; i++) ra[i] = sQ[(ty * 4 + i) * 65 + kk];
            #pragma unroll
            for (int j = 0; j < 4; j++) rb[j] = sK[(tx * 4 + j) * 65 + kk];
            #pragma unroll
            for (int i = 0; i < 4; i++)
                #pragma unroll
                for (int j = 0; j < 4; j++)
                    acc[i][j] += ra[i] * rb[j];
        }
        #pragma unroll
        for (int j = 0; j < 4; j++) {
            int c = tx * 4 + j;
            bool keep = mask[b * Ss + k0 + c] != 0;
            #pragma unroll
            for (int i = 0; i < 4; i++) {
                float vv = keep ? acc[i][j] : -1e20f;
                sS[(ty * 4 + i) * 65 + c] = vv * 0.125f;
            }
        }
        __syncthreads();

        if (tid < 64) {
            int r = tid;
            float tm = -INFINITY;
            #pragma unroll 8
            for (int c = 0; c < 64; c++) tm = fmaxf(tm, sS[r * 65 + c]);
            float mn = fmaxf(m_i, tm);
            float ps = 0.f;
            #pragma unroll 8
            for (int c = 0; c < 64; c++) {
                float p = __expf(sS[r * 65 + c] - mn);
                sS[r * 65 + c] = p;
                ps += p;
            }
            float sc = (m_i == -INFINITY) ? 0.f : __expf(m_i - mn);
            l_i = l_i * sc + ps;
            m_i = mn;
            sScale[r] = sc;
        }
        __syncthreads();

        #pragma unroll
        for (int i = 0; i < 4; i++) {
            float sc = sScale[ty * 4 + i];
            #pragma unroll
            for (int j = 0; j < 4; j++) oacc[i][j] *= sc;
        }
        #pragma unroll
        for (int kk = 0; kk < 64; kk++) {
            float rp[4], rv[4];
            #pragma unroll
            for (int i = 0; i < 4; i++) rp[i] = sS[(ty * 4 + i) * 65 + kk];
            #pragma unroll
            for (int j = 0; j < 4; j++) rv[j] = sV[kk * 65 + tx * 4 + j];
            #pragma unroll
            for (int i = 0; i < 4; i++)
                #pragma unroll
                for (int j = 0; j < 4; j++)
                    oacc[i][j] += rp[i] * rv[j];
        }
        __syncthreads();
    }

    if (tid < 64) sL[tid] = l_i;
    __syncthreads();
    #pragma unroll
    for (int i = 0; i < 4; i++) {
        int r = ty * 4 + i;
        float inv = 1.f / sL[r];
        #pragma unroll
        for (int j = 0; j < 4; j++)
            out[base + (size_t)(q0 + r) * Dd + tx * 4 + j] = oacc[i][j] * inv;
    }
}

// ---------------- residual add + LayerNorm (+optional mask mult) --------------
__global__ void ln_residual_kernel(const float* __restrict__ xin, const float* __restrict__ res,
                                   const float* __restrict__ g, const float* __restrict__ beta,
                                   float* __restrict__ outp, const int* __restrict__ mask) {
    __shared__ float red[8];
    int row = blockIdx.x, tid = threadIdx.x;
    const float* xr = xin + (size_t)row * Dd;
    const float* rr = res + (size_t)row * Dd;
    float v0 = xr[tid] + rr[tid];
    float v1 = xr[tid + 256] + rr[tid + 256];

    float s = v0 + v1;
    #pragma unroll
    for (int o = 16; o > 0; o >>= 1) s += __shfl_down_sync(0xffffffffu, s, o);
    if ((tid & 31) == 0) red[tid >> 5] = s;
    __syncthreads();
    if (tid < 8) {
        float t = red[tid];
        #pragma unroll
        for (int o = 4; o > 0; o >>= 1) t += __shfl_down_sync(0xffu, t, o);
        if (tid == 0) red[0] = t;
    }
    __syncthreads();
    float mean = red[0] * (1.f / Dd);
    __syncthreads();

    float d0 = v0 - mean, d1 = v1 - mean;
    float vs = d0 * d0 + d1 * d1;
    #pragma unroll
    for (int o = 16; o > 0; o >>= 1) vs += __shfl_down_sync(0xffffffffu, vs, o);
    if ((tid & 31) == 0) red[tid >> 5] = vs;
    __syncthreads();
    if (tid < 8) {
        float t = red[tid];
        #pragma unroll
        for (int o = 4; o > 0; o >>= 1) t += __shfl_down_sync(0xffu, t, o);
        if (tid == 0) red[0] = t;
    }
    __syncthreads();
    float var = red[0] * (1.f / Dd);
    float inv = rsqrtf(var + 1e-5f);
    float mf = mask ? (float)mask[row] : 1.f;
    outp[(size_t)row * Dd + tid]       = (d0 * inv * g[tid]       + beta[tid])       * mf;
    outp[(size_t)row * Dd + tid + 256] = (d1 * inv * g[tid + 256] + beta[tid + 256]) * mf;
}

// ---------------- masked mean pool over sequence ------------------------------
__global__ void pool_kernel(const int* __restrict__ mask, float* __restrict__ out) {
    __shared__ float red[8];
    int b = blockIdx.x, tid = threadIdx.x;
    float s0 = 0.f, s1 = 0.f;
    for (int t = 0; t < Ss; t++) {
        const float* xr = g_x + ((size_t)(b * Ss + t)) * Dd;
        s0 += xr[tid];
        s1 += xr[tid + 256];
    }
    float c = 0.f;
    for (int t = tid; t < Ss; t += 256) c += (float)mask[b * Ss + t];
    #pragma unroll
    for (int o = 16; o > 0; o >>= 1) c += __shfl_down_sync(0xffffffffu, c, o);
    if ((tid & 31) == 0) red[tid >> 5] = c;
    __syncthreads();
    if (tid < 8) {
        float t2 = red[tid];
        #pragma unroll
        for (int o = 4; o > 0; o >>= 1) t2 += __shfl_down_sync(0xffu, t2, o);
        if (tid == 0) red[0] = t2;
    }
    __syncthreads();
    float div = fmaxf(red[0], 1e-20f);
    out[b * Dd + tid]       = s0 / div;
    out[b * Dd + tid + 256] = s1 / div;
}

// ---------------- host orchestration ------------------------------------------
extern "C" void kernel_launch(void* const* d_in, const int* in_sizes, int n_in,
                              void* d_out, int out_size) {
    (void)in_sizes; (void)n_in; (void)out_size;
    const int*   inp   = (const int*)  d_in[0];
    const int*   mask  = (const int*)  d_in[1];
    const float* emb   = (const float*)d_in[2];
    const float* pos   = (const float*)d_in[3];
    const float* Wq    = (const float*)d_in[4];
    const float* bq    = (const float*)d_in[5];
    const float* Wk    = (const float*)d_in[6];
    const float* bk    = (const float*)d_in[7];
    const float* Wv    = (const float*)d_in[8];
    const float* bv    = (const float*)d_in[9];
    const float* Wo    = (const float*)d_in[10];
    const float* bo    = (const float*)d_in[11];
    const float* ln1g  = (const float*)d_in[12];
    const float* ln1b  = (const float*)d_in[13];
    const float* W1    = (const float*)d_in[14];
    const float* b1    = (const float*)d_in[15];
    const float* W2    = (const float*)d_in[16];
    const float* b2    = (const float*)d_in[17];
    const float* ln2g  = (const float*)d_in[18];
    const float* ln2b  = (const float*)d_in[19];
    float* out = (float*)d_out;

    float *xp, *qp, *kp, *vp, *ap, *pp, *hp;
    __half *xb, *hb, *wb;
    cudaGetSymbolAddress((void**)&xp, g_x);
    cudaGetSymbolAddress((void**)&qp, g_q);
    cudaGetSymbolAddress((void**)&kp, g_k);
    cudaGetSymbolAddress((void**)&vp, g_v);
    cudaGetSymbolAddress((void**)&ap, g_attn);
    cudaGetSymbolAddress((void**)&pp, g_proj);
    cudaGetSymbolAddress((void**)&hp, g_h);
    cudaGetSymbolAddress((void**)&xb, g_xb);
    cudaGetSymbolAddress((void**)&hb, g_hb);
    cudaGetSymbolAddress((void**)&wb, g_wb);

    const int attn_smem = ATTN_SMEM_FLOATS * (int)sizeof(float);
    cudaFuncSetAttribute(attn_kernel, cudaFuncAttributeMaxDynamicSharedMemorySize, attn_smem);
    cudaFuncSetAttribute(gemm_hmma<false>, cudaFuncAttributeMaxDynamicSharedMemorySize, GEMM_SMEM_BYTES);
    cudaFuncSetAttribute(gemm_hmma<true>,  cudaFuncAttributeMaxDynamicSharedMemorySize, GEMM_SMEM_BYTES);

    embed_kernel<<<ROWS, 256>>>(inp, mask, emb, pos);

    dim3 gD(Dd / 128, ROWS / 128);
    dim3 gF(FF / 128, ROWS / 128);
    dim3 gA(Ss / 64, Bb * Hh);

    const int cvActD = (ROWS * Dd) / 1024;
    const int cvActF = (ROWS * FF) / 1024;
    const int cvWdd  = (Dd * Dd) / 1024;
    const int cvW1   = (FF * Dd) / 1024;
    const int cvW2   = (Dd * FF) / 1024;

    for (int l = 0; l < Ll; l++) {
        const float* Wq_l = Wq + (size_t)l * Dd * Dd;
        const float* Wk_l = Wk + (size_t)l * Dd * Dd;
        const float* Wv_l = Wv + (size_t)l * Dd * Dd;
        const float* Wo_l = Wo + (size_t)l * Dd * Dd;
        const float* W1_l = W1 + (size_t)l * FF * Dd;
        const float* W2_l = W2 + (size_t)l * Dd * FF;
        const float* bq_l = bq + (size_t)l * Dd;
        const float* bk_l = bk + (size_t)l * Dd;
        const float* bv_l = bv + (size_t)l * Dd;
        const float* bo_l = bo + (size_t)l * Dd;
        const float* b1_l = b1 + (size_t)l * FF;
        const float* b2_l = b2 + (size_t)l * Dd;

        conv_split<true><<<cvActD, 256>>>(xp, xb, Dd);
        conv_split<false><<<cvWdd, 256>>>(Wq_l, wb, Dd);
        gemm_hmma<false><<<gD, 256, GEMM_SMEM_BYTES>>>(xb, wb, bq_l, qp, ROWS, Dd, KP1);
        conv_split<false><<<cvWdd, 256>>>(Wk_l, wb, Dd);
        gemm_hmma<false><<<gD, 256, GEMM_SMEM_BYTES>>>(xb, wb, bk_l, kp, ROWS, Dd, KP1);
        conv_split<false><<<cvWdd, 256>>>(Wv_l, wb, Dd);
        gemm_hmma<false><<<gD, 256, GEMM_SMEM_BYTES>>>(xb, wb, bv_l, vp, ROWS, Dd, KP1);

        attn_kernel<<<gA, 256, attn_smem>>>(qp, kp, vp, mask, ap);

        conv_split<true><<<cvActD, 256>>>(ap, xb, Dd);
        conv_split<false><<<cvWdd, 256>>>(Wo_l, wb, Dd);
        gemm_hmma<false><<<gD, 256, GEMM_SMEM_BYTES>>>(xb, wb, bo_l, pp, ROWS, Dd, KP1);
        ln_residual_kernel<<<ROWS, 256>>>(xp, pp, ln1g + (size_t)l * Dd, ln1b + (size_t)l * Dd,
                                          xp, (const int*)nullptr);

        conv_split<true><<<cvActD, 256>>>(xp, xb, Dd);
        conv_split<false><<<cvW1, 256>>>(W1_l, wb, Dd);
        gemm_hmma<true><<<gF, 256, GEMM_SMEM_BYTES>>>(xb, wb, b1_l, hp, ROWS, FF, KP1);
        conv_split<true><<<cvActF, 256>>>(hp, hb, FF);
        conv_split<false><<<cvW2, 256>>>(W2_l, wb, FF);
        gemm_hmma<false><<<gD, 256, GEMM_SMEM_BYTES>>>(hb, wb, b2_l, pp, ROWS, Dd, KP2);
        ln_residual_kernel<<<ROWS, 256>>>(xp, pp, ln2g + (size_t)l * Dd, ln2b + (size_t)l * Dd,
                                          xp, mask);
    }

    pool_kernel<<<Bb, 256>>>(mask, out);
}

// round 15
// speedup vs baseline: 2.2259x; 1.4180x over previous
#include <cuda_runtime.h>
#include <cuda_fp16.h>
#include <cuda_bf16.h>
#include <math.h>
#include <stdint.h>
#include <string.h>

// Problem constants
#define Bb   16
#define Ss   1024
#define Dd   512
#define Hh   8
#define DH   64
#define Ll   6
#define FF   2048
#define ROWS (Bb*Ss)       // 16384
#define KP1  (2*Dd)        // 1024  (fp16 2-term split K')
#define KP2  (2*FF)        // 4096
#define BH   (Bb*Hh)       // 128

// ---------------- scratch (device globals; no runtime allocation) -------------
__device__ float g_x[ROWS*Dd];
__device__ float g_q[ROWS*Dd];
__device__ float g_k[ROWS*Dd];
__device__ float g_v[ROWS*Dd];
__device__ float g_attn[ROWS*Dd];
__device__ float g_proj[ROWS*Dd];
__device__ float g_h[ROWS*FF];
__device__ __half g_xb[(size_t)ROWS*KP1];
__device__ __half g_hb[(size_t)ROWS*KP2];
__device__ __half g_wb[(size_t)FF*KP1];
// per-head split-bf16 Q/K [BH,S,64] and V transposed [BH,64,S]  (R7-validated)
__device__ __nv_bfloat16 g_qhh[(size_t)BH*Ss*64];
__device__ __nv_bfloat16 g_qll[(size_t)BH*Ss*64];
__device__ __nv_bfloat16 g_khh[(size_t)BH*Ss*64];
__device__ __nv_bfloat16 g_kll[(size_t)BH*Ss*64];
__device__ __nv_bfloat16 g_vhh[(size_t)BH*Ss*64];
__device__ __nv_bfloat16 g_vll[(size_t)BH*Ss*64];

// ======================= PTX helpers (portable, sm_80+) =======================
__device__ __forceinline__ uint32_t smem_u32(const void* p) {
    uint32_t a;
    asm("{ .reg .u64 t; cvta.to.shared.u64 t, %1; cvt.u32.u64 %0, t; }" : "=r"(a) : "l"(p));
    return a;
}
#define CP_ASYNC16(dst, src) \
    asm volatile("cp.async.cg.shared.global [%0], [%1], 16;" :: "r"(dst), "l"(src) : "memory")
#define CP_COMMIT() asm volatile("cp.async.commit_group;" ::: "memory")
#define CP_WAIT(n)  asm volatile("cp.async.wait_group %0;" :: "n"(n) : "memory")

#define SWZ128(o) ((o) ^ (((o) >> 3) & 0x70))

__device__ __forceinline__ void ldmatrix_x4(uint32_t& r0, uint32_t& r1, uint32_t& r2, uint32_t& r3,
                                            uint32_t addr) {
    asm volatile("ldmatrix.sync.aligned.m8n8.x4.shared.b16 {%0,%1,%2,%3}, [%4];"
                 : "=r"(r0), "=r"(r1), "=r"(r2), "=r"(r3) : "r"(addr));
}
// fp16 MMA (GEMM path)
__device__ __forceinline__ void mma_f16(float& c0, float& c1, float& c2, float& c3,
                                        uint32_t a0, uint32_t a1, uint32_t a2, uint32_t a3,
                                        uint32_t b0, uint32_t b1) {
    asm volatile("mma.sync.aligned.m16n8k16.row.col.f32.f16.f16.f32 "
                 "{%0,%1,%2,%3}, {%4,%5,%6,%7}, {%8,%9}, {%10,%11,%12,%13};"
                 : "=f"(c0), "=f"(c1), "=f"(c2), "=f"(c3)
                 : "r"(a0), "r"(a1), "r"(a2), "r"(a3), "r"(b0), "r"(b1),
                   "f"(c0), "f"(c1), "f"(c2), "f"(c3));
}
// bf16 MMA (attention path, R7-validated)
__device__ __forceinline__ void mma_bf16(float& c0, float& c1, float& c2, float& c3,
                                         uint32_t a0, uint32_t a1, uint32_t a2, uint32_t a3,
                                         uint32_t b0, uint32_t b1) {
    asm volatile("mma.sync.aligned.m16n8k16.row.col.f32.bf16.bf16.f32 "
                 "{%0,%1,%2,%3}, {%4,%5,%6,%7}, {%8,%9}, {%10,%11,%12,%13};"
                 : "=f"(c0), "=f"(c1), "=f"(c2), "=f"(c3)
                 : "r"(a0), "r"(a1), "r"(a2), "r"(a3), "r"(b0), "r"(b1),
                   "f"(c0), "f"(c1), "f"(c2), "f"(c3));
}

// ldmatrix x4 address for a 16x16 block inside a [rows x 128B] SW128 tile (R7).
__device__ __forceinline__ uint32_t ldsm_addr(uint32_t tilebase, int base16, int kk) {
    int lane = threadIdx.x & 31;
    int g = lane >> 3, r8 = lane & 7;
    int r = base16 + (g & 1) * 8 + r8;
    int bc = kk * 32 + (g >> 1) * 16;
    return tilebase + (uint32_t)(r * 128 + (bc ^ ((r & 7) * 16)));
}

// ================= split-fp16 conversion (GEMM path, R12) =====================
template <bool AMODE>
__global__ void conv_split(const float* __restrict__ src, __half* __restrict__ dst, int K) {
    size_t lin = ((size_t)blockIdx.x * 256 + threadIdx.x) * 4;
    int r = (int)(lin / K);
    int k = (int)(lin % K);
    float4 v = *(const float4*)(src + lin);
    float vv[4] = {v.x, v.y, v.z, v.w};
    __half h[4], lo[4];
    #pragma unroll
    for (int i = 0; i < 4; i++) {
        h[i]  = __float2half(vv[i]);
        lo[i] = __float2half(vv[i] - __half2float(h[i]));
    }
    size_t base = (size_t)r * (2 * (size_t)K) + k;
    uint32_t hp0, hp1, lp0, lp1;
    {
        __half2 a = __halves2half2(h[0], h[1]), b = __halves2half2(h[2], h[3]);
        __half2 c = __halves2half2(lo[0], lo[1]), d = __halves2half2(lo[2], lo[3]);
        memcpy(&hp0, &a, 4); memcpy(&hp1, &b, 4); memcpy(&lp0, &c, 4); memcpy(&lp1, &d, 4);
    }
    uint2 hv = make_uint2(hp0, hp1);
    uint2 lv = make_uint2(lp0, lp1);
    *(uint2*)(dst + base)     = hv;
    *(uint2*)(dst + base + K) = AMODE ? lv : hv;
}

// ============ attention head-split conversions (bf16, R7-validated) ===========
__global__ void conv_heads(const float* __restrict__ src,
                           __nv_bfloat16* __restrict__ hi, __nv_bfloat16* __restrict__ lo) {
    int row = blockIdx.x, tid = threadIdx.x;       // 128 threads
    int d = tid * 4;
    float4 v = *(const float4*)(src + (size_t)row * Dd + d);
    int b = row >> 10, s = row & 1023, h = d >> 6, dl = d & 63;
    size_t ob = ((size_t)(b * Hh + h) * Ss + s) * 64 + dl;
    float vv[4] = {v.x, v.y, v.z, v.w};
    __nv_bfloat16 hh[4], ll[4];
    #pragma unroll
    for (int i = 0; i < 4; i++) {
        hh[i] = __float2bfloat16(vv[i]);
        ll[i] = __float2bfloat16(vv[i] - __bfloat162float(hh[i]));
    }
    uint32_t a0, a1, b0, b1;
    { __nv_bfloat162 t0(hh[0], hh[1]), t1(hh[2], hh[3]), t2(ll[0], ll[1]), t3(ll[2], ll[3]);
      memcpy(&a0, &t0, 4); memcpy(&a1, &t1, 4); memcpy(&b0, &t2, 4); memcpy(&b1, &t3, 4); }
    *(uint2*)(hi + ob) = make_uint2(a0, a1);
    *(uint2*)(lo + ob) = make_uint2(b0, b1);
}

__global__ void conv_vT(const float* __restrict__ src,
                        __nv_bfloat16* __restrict__ hi, __nv_bfloat16* __restrict__ lo) {
    __shared__ float tile[64][65];
    int s0 = blockIdx.x * 64, bh = blockIdx.y;
    int b = bh >> 3, h = bh & 7;
    int tid = threadIdx.x;                          // 256 threads
    for (int p = tid; p < 1024; p += 256) {
        int r = p >> 4, c4 = (p & 15) * 4;
        float4 v = *(const float4*)(src + ((size_t)(b * Ss + s0 + r)) * Dd + h * 64 + c4);
        tile[r][c4 + 0] = v.x; tile[r][c4 + 1] = v.y;
        tile[r][c4 + 2] = v.z; tile[r][c4 + 3] = v.w;
    }
    __syncthreads();
    for (int p = tid; p < 2048; p += 256) {
        int dd = p >> 5, sc = (p & 31) * 2;
        float v0 = tile[sc][dd], v1 = tile[sc + 1][dd];
        __nv_bfloat16 h0 = __float2bfloat16(v0), h1 = __float2bfloat16(v1);
        __nv_bfloat16 l0 = __float2bfloat16(v0 - __bfloat162float(h0));
        __nv_bfloat16 l1 = __float2bfloat16(v1 - __bfloat162float(h1));
        uint32_t ph, pl;
        { __nv_bfloat162 th(h0, h1), tl(l0, l1); memcpy(&ph, &th, 4); memcpy(&pl, &tl, 4); }
        size_t ob = ((size_t)bh * 64 + dd) * Ss + s0 + sc;
        *(uint32_t*)(hi + ob) = ph;
        *(uint32_t*)(lo + ob) = pl;
    }
}

// ================= HMMA GEMM (fp16, R12 champion — unchanged) =================
#define GEMM_SMEM_BYTES (4 * 16384)
template <bool RELU>
__global__ void __launch_bounds__(256, 2) gemm_hmma(
    const __half* __restrict__ A, const __half* __restrict__ W,
    const float* __restrict__ bias, float* __restrict__ C, int M, int N, int Kp) {
    extern __shared__ char smem[];
    const uint32_t sb = smem_u32(smem);
    const int tid = threadIdx.x;
    const int lane = tid & 31, wid = tid >> 5;
    const int wm = wid & 1, wn = wid >> 1;
    const int m0 = blockIdx.y * 128, n0 = blockIdx.x * 128;

    const uint32_t offA[2] = {0u, 32768u};
    const uint32_t offB[2] = {16384u, 49152u};

    const __half* Ap = A + (size_t)m0 * Kp;
    const __half* Bp = W + (size_t)n0 * Kp;
    const int nc = Kp >> 6;

    const int lrow = tid >> 1;
    const int lch0 = (tid & 1) * 4;

    float acc[4][4][4];
    #pragma unroll
    for (int i = 0; i < 4; i++)
        #pragma unroll
        for (int j = 0; j < 4; j++)
            #pragma unroll
            for (int r = 0; r < 4; r++) acc[i][j][r] = 0.f;

    auto issue = [&](int i, int b) {
        const __half* Ac = Ap + (size_t)i * 64;
        const __half* Bc = Bp + (size_t)i * 64;
        #pragma unroll
        for (int j = 0; j < 4; j++) {
            int ch = lch0 + j;
            uint32_t so = SWZ128((uint32_t)(lrow * 128 + ch * 16));
            CP_ASYNC16(sb + offA[b] + so, Ac + (size_t)lrow * Kp + ch * 8);
            CP_ASYNC16(sb + offB[b] + so, Bc + (size_t)lrow * Kp + ch * 8);
        }
    };

    issue(0, 0); CP_COMMIT();

    for (int i = 0; i < nc; i++) {
        int b = i & 1;
        if (i + 1 < nc) { issue(i + 1, b ^ 1); CP_COMMIT(); CP_WAIT(1); }
        else            { CP_WAIT(0); }
        __syncthreads();

        const uint32_t baA = sb + offA[b];
        const uint32_t baB = sb + offB[b];
        #pragma unroll
        for (int kk = 0; kk < 4; kk++) {
            uint32_t a[4][4];
            {
                int r = lane & 15, half = lane >> 4;
                #pragma unroll
                for (int mi = 0; mi < 4; mi++) {
                    int row = wm * 64 + mi * 16 + r;
                    uint32_t off = (uint32_t)(row * 128)
                                 + (uint32_t)((kk * 32 + half * 16) ^ ((row & 7) * 16));
                    ldmatrix_x4(a[mi][0], a[mi][1], a[mi][2], a[mi][3], baA + off);
                }
            }
            uint32_t bfr[4][2];
            {
                int g = lane >> 3, r8 = lane & 7;
                #pragma unroll
                for (int p = 0; p < 2; p++) {
                    int row = wn * 32 + p * 16 + (g & 1) * 8 + r8;
                    uint32_t off = (uint32_t)(row * 128)
                                 + (uint32_t)((kk * 32 + (g >> 1) * 16) ^ ((row & 7) * 16));
                    uint32_t r0, r1, r2, r3;
                    ldmatrix_x4(r0, r1, r2, r3, baB + off);
                    bfr[p * 2 + 0][0] = r0; bfr[p * 2 + 0][1] = r2;
                    bfr[p * 2 + 1][0] = r1; bfr[p * 2 + 1][1] = r3;
                }
            }
            #pragma unroll
            for (int mi = 0; mi < 4; mi++)
                #pragma unroll
                for (int ni = 0; ni < 4; ni++)
                    mma_f16(acc[mi][ni][0], acc[mi][ni][1], acc[mi][ni][2], acc[mi][ni][3],
                            a[mi][0], a[mi][1], a[mi][2], a[mi][3],
                            bfr[ni][0], bfr[ni][1]);
        }
        __syncthreads();
    }

    #pragma unroll
    for (int mi = 0; mi < 4; mi++) {
        int row0 = m0 + wm * 64 + mi * 16 + (lane >> 2);
        #pragma unroll
        for (int ni = 0; ni < 4; ni++) {
            int col = n0 + wn * 32 + ni * 8 + (lane & 3) * 2;
            float b0 = bias[col], b1 = bias[col + 1];
            float2 v0 = make_float2(acc[mi][ni][0] + b0, acc[mi][ni][1] + b1);
            float2 v1 = make_float2(acc[mi][ni][2] + b0, acc[mi][ni][3] + b1);
            if (RELU) {
                v0.x = fmaxf(v0.x, 0.f); v0.y = fmaxf(v0.y, 0.f);
                v1.x = fmaxf(v1.x, 0.f); v1.y = fmaxf(v1.y, 0.f);
            }
            *(float2*)(C + (size_t)row0 * N + col)       = v0;
            *(float2*)(C + (size_t)(row0 + 8) * N + col) = v1;
        }
    }
}

// ========= HMMA flash attention (split-bf16, 3-pass — R7-validated) ===========
#define A_QH   0
#define A_QL   16384
#define A_KV   32768
#define A_MSK  98304
#define ATT_SMEM (98304 + 512)

__global__ void __launch_bounds__(256) attn_mma(
    const __nv_bfloat16* __restrict__ qh_, const __nv_bfloat16* __restrict__ ql_,
    const __nv_bfloat16* __restrict__ kh_, const __nv_bfloat16* __restrict__ kl_,
    const __nv_bfloat16* __restrict__ vh_, const __nv_bfloat16* __restrict__ vl_,
    const int* __restrict__ mask, float* __restrict__ out) {
    extern __shared__ char smem[];
    const uint32_t sb = smem_u32(smem);
    const int tid = threadIdx.x, lane = tid & 31, w = tid >> 5;
    const int bh = blockIdx.y, b = bh >> 3, h = bh & 7;
    const int q0 = blockIdx.x * 128;
    const int R0 = w * 16;

    const __nv_bfloat16* qsrc[2] = {qh_ + (size_t)bh * Ss * 64, ql_ + (size_t)bh * Ss * 64};
    const __nv_bfloat16* ksrc[2] = {kh_ + (size_t)bh * Ss * 64, kl_ + (size_t)bh * Ss * 64};
    const __nv_bfloat16* vsrc[2] = {vh_ + (size_t)bh * 64 * Ss, vl_ + (size_t)bh * 64 * Ss};

    auto issue_kv = [&](int t, int buf) {
        int k0 = t * 64;
        uint32_t dbase = sb + A_KV + buf * 32768;
        #pragma unroll
        for (int j = 0; j < 8; j++) {
            int c = j * 256 + tid;
            int tn = c >> 9, wv = c & 511;
            int r = wv >> 3, ch = wv & 7;
            uint32_t dst = dbase + tn * 8192 + SWZ128((uint32_t)(r * 128 + ch * 16));
            const __nv_bfloat16* src;
            if (tn == 0)      src = ksrc[0] + (size_t)(k0 + r) * 64 + ch * 8;
            else if (tn == 1) src = ksrc[1] + (size_t)(k0 + r) * 64 + ch * 8;
            else if (tn == 2) src = vsrc[0] + (size_t)r * Ss + k0 + ch * 8;
            else              src = vsrc[1] + (size_t)r * Ss + k0 + ch * 8;
            CP_ASYNC16(dst, src);
        }
        if (tid < 64) {
            float* smM = (float*)(smem + A_MSK + buf * 256);
            smM[tid] = mask[b * Ss + k0 + tid] ? 0.f : -1e20f;
        }
    };

    #pragma unroll
    for (int j = 0; j < 8; j++) {
        int c = j * 256 + tid;
        int tn = c >> 10, wv = c & 1023;
        int r = wv >> 3, ch = wv & 7;
        uint32_t dst = sb + (tn ? A_QL : A_QH) + SWZ128((uint32_t)(r * 128 + ch * 16));
        CP_ASYNC16(dst, qsrc[tn] + (size_t)(q0 + r) * 64 + ch * 8);
    }
    issue_kv(0, 0);
    CP_COMMIT();

    uint32_t qhf[4][4], qlf[4][4];
    float oacc[8][4];
    #pragma unroll
    for (int j = 0; j < 8; j++)
        #pragma unroll
        for (int r = 0; r < 4; r++) oacc[j][r] = 0.f;
    float m0 = -INFINITY, m1 = -INFINITY, l0 = 0.f, l1 = 0.f;

    for (int t = 0; t < 16; t++) {
        int buf = t & 1;
        if (t < 15) { issue_kv(t + 1, buf ^ 1); CP_COMMIT(); CP_WAIT(1); }
        else        { CP_WAIT(0); }
        __syncthreads();

        if (t == 0) {
            #pragma unroll
            for (int kk = 0; kk < 4; kk++) {
                ldmatrix_x4(qhf[kk][0], qhf[kk][1], qhf[kk][2], qhf[kk][3],
                            ldsm_addr(sb + A_QH, R0, kk));
                ldmatrix_x4(qlf[kk][0], qlf[kk][1], qlf[kk][2], qlf[kk][3],
                            ldsm_addr(sb + A_QL, R0, kk));
            }
        }

        const uint32_t bKH = sb + A_KV + buf * 32768;
        const uint32_t bKL = bKH + 8192;
        const uint32_t bVH = bKH + 16384;
        const uint32_t bVL = bKH + 24576;
        const float* smM = (const float*)(smem + A_MSK + buf * 256);

        float sacc[8][4];
        #pragma unroll
        for (int j = 0; j < 8; j++)
            #pragma unroll
            for (int r = 0; r < 4; r++) sacc[j][r] = 0.f;

        #pragma unroll
        for (int kk = 0; kk < 4; kk++) {
            uint32_t kb[8][2];
            #pragma unroll
            for (int nt = 0; nt < 4; nt++) {
                uint32_t r0, r1, r2, r3;
                ldmatrix_x4(r0, r1, r2, r3, ldsm_addr(bKH, nt * 16, kk));
                kb[nt * 2 + 0][0] = r0; kb[nt * 2 + 0][1] = r2;
                kb[nt * 2 + 1][0] = r1; kb[nt * 2 + 1][1] = r3;
            }
            #pragma unroll
            for (int j = 0; j < 8; j++)
                mma_bf16(sacc[j][0], sacc[j][1], sacc[j][2], sacc[j][3],
                         qhf[kk][0], qhf[kk][1], qhf[kk][2], qhf[kk][3], kb[j][0], kb[j][1]);
            #pragma unroll
            for (int j = 0; j < 8; j++)
                mma_bf16(sacc[j][0], sacc[j][1], sacc[j][2], sacc[j][3],
                         qlf[kk][0], qlf[kk][1], qlf[kk][2], qlf[kk][3], kb[j][0], kb[j][1]);
            #pragma unroll
            for (int nt = 0; nt < 4; nt++) {
                uint32_t r0, r1, r2, r3;
                ldmatrix_x4(r0, r1, r2, r3, ldsm_addr(bKL, nt * 16, kk));
                kb[nt * 2 + 0][0] = r0; kb[nt * 2 + 0][1] = r2;
                kb[nt * 2 + 1][0] = r1; kb[nt * 2 + 1][1] = r3;
            }
            #pragma unroll
            for (int j = 0; j < 8; j++)
                mma_bf16(sacc[j][0], sacc[j][1], sacc[j][2], sacc[j][3],
                         qhf[kk][0], qhf[kk][1], qhf[kk][2], qhf[kk][3], kb[j][0], kb[j][1]);
        }

        float mt0 = -INFINITY, mt1 = -INFINITY;
        #pragma unroll
        for (int j = 0; j < 8; j++) {
            int c0 = j * 8 + (lane & 3) * 2;
            float mk0 = smM[c0], mk1 = smM[c0 + 1];
            sacc[j][0] = (sacc[j][0] + mk0) * 0.125f;
            sacc[j][1] = (sacc[j][1] + mk1) * 0.125f;
            sacc[j][2] = (sacc[j][2] + mk0) * 0.125f;
            sacc[j][3] = (sacc[j][3] + mk1) * 0.125f;
            mt0 = fmaxf(mt0, fmaxf(sacc[j][0], sacc[j][1]));
            mt1 = fmaxf(mt1, fmaxf(sacc[j][2], sacc[j][3]));
        }
        mt0 = fmaxf(mt0, __shfl_xor_sync(0xffffffffu, mt0, 1));
        mt0 = fmaxf(mt0, __shfl_xor_sync(0xffffffffu, mt0, 2));
        mt1 = fmaxf(mt1, __shfl_xor_sync(0xffffffffu, mt1, 1));
        mt1 = fmaxf(mt1, __shfl_xor_sync(0xffffffffu, mt1, 2));

        float mn0 = fmaxf(m0, mt0), mn1 = fmaxf(m1, mt1);
        float sc0 = __expf(m0 - mn0), sc1 = __expf(m1 - mn1);

        uint32_t phi[4][4], plo[4][4];
        float ps0 = 0.f, ps1 = 0.f;
        #pragma unroll
        for (int j = 0; j < 8; j++) {
            float p0 = __expf(sacc[j][0] - mn0);
            float p1 = __expf(sacc[j][1] - mn0);
            float p2 = __expf(sacc[j][2] - mn1);
            float p3 = __expf(sacc[j][3] - mn1);
            ps0 += p0 + p1; ps1 += p2 + p3;
            __nv_bfloat16 h0 = __float2bfloat16(p0), h1 = __float2bfloat16(p1);
            __nv_bfloat16 h2 = __float2bfloat16(p2), h3 = __float2bfloat16(p3);
            uint32_t H01, H23, L01, L23;
            { __nv_bfloat162 a(h0, h1), c(h2, h3);
              __nv_bfloat162 e(__float2bfloat16(p0 - __bfloat162float(h0)),
                               __float2bfloat16(p1 - __bfloat162float(h1)));
              __nv_bfloat162 f(__float2bfloat16(p2 - __bfloat162float(h2)),
                               __float2bfloat16(p3 - __bfloat162float(h3)));
              memcpy(&H01, &a, 4); memcpy(&H23, &c, 4);
              memcpy(&L01, &e, 4); memcpy(&L23, &f, 4); }
            int kk = j >> 1, o = (j & 1) * 2;
            phi[kk][o + 0] = H01; phi[kk][o + 1] = H23;
            plo[kk][o + 0] = L01; plo[kk][o + 1] = L23;
        }
        ps0 += __shfl_xor_sync(0xffffffffu, ps0, 1);
        ps0 += __shfl_xor_sync(0xffffffffu, ps0, 2);
        ps1 += __shfl_xor_sync(0xffffffffu, ps1, 1);
        ps1 += __shfl_xor_sync(0xffffffffu, ps1, 2);
        l0 = l0 * sc0 + ps0; l1 = l1 * sc1 + ps1;
        m0 = mn0; m1 = mn1;

        #pragma unroll
        for (int j = 0; j < 8; j++) {
            oacc[j][0] *= sc0; oacc[j][1] *= sc0;
            oacc[j][2] *= sc1; oacc[j][3] *= sc1;
        }

        #pragma unroll
        for (int kk = 0; kk < 4; kk++) {
            uint32_t vb[8][2];
            #pragma unroll
            for (int nt = 0; nt < 4; nt++) {
                uint32_t r0, r1, r2, r3;
                ldmatrix_x4(r0, r1, r2, r3, ldsm_addr(bVH, nt * 16, kk));
                vb[nt * 2 + 0][0] = r0; vb[nt * 2 + 0][1] = r2;
                vb[nt * 2 + 1][0] = r1; vb[nt * 2 + 1][1] = r3;
            }
            #pragma unroll
            for (int j = 0; j < 8; j++)
                mma_bf16(oacc[j][0], oacc[j][1], oacc[j][2], oacc[j][3],
                         phi[kk][0], phi[kk][1], phi[kk][2], phi[kk][3], vb[j][0], vb[j][1]);
            #pragma unroll
            for (int j = 0; j < 8; j++)
                mma_bf16(oacc[j][0], oacc[j][1], oacc[j][2], oacc[j][3],
                         plo[kk][0], plo[kk][1], plo[kk][2], plo[kk][3], vb[j][0], vb[j][1]);
            #pragma unroll
            for (int nt = 0; nt < 4; nt++) {
                uint32_t r0, r1, r2, r3;
                ldmatrix_x4(r0, r1, r2, r3, ldsm_addr(bVL, nt * 16, kk));
                vb[nt * 2 + 0][0] = r0; vb[nt * 2 + 0][1] = r2;
                vb[nt * 2 + 1][0] = r1; vb[nt * 2 + 1][1] = r3;
            }
            #pragma unroll
            for (int j = 0; j < 8; j++)
                mma_bf16(oacc[j][0], oacc[j][1], oacc[j][2], oacc[j][3],
                         phi[kk][0], phi[kk][1], phi[kk][2], phi[kk][3], vb[j][0], vb[j][1]);
        }
        __syncthreads();
    }

    float inv0 = 1.f / l0, inv1 = 1.f / l1;
    int row0 = q0 + R0 + (lane >> 2);
    #pragma unroll
    for (int j = 0; j < 8; j++) {
        int col = h * 64 + j * 8 + (lane & 3) * 2;
        *(float2*)(out + ((size_t)(b * Ss + row0)) * Dd + col) =
            make_float2(oacc[j][0] * inv0, oacc[j][1] * inv0);
        *(float2*)(out + ((size_t)(b * Ss + row0 + 8)) * Dd + col) =
            make_float2(oacc[j][2] * inv1, oacc[j][3] * inv1);
    }
}

// ---------------- embedding + positional + mask -------------------------------
__global__ void embed_kernel(const int* __restrict__ inp, const int* __restrict__ mask,
                             const float* __restrict__ emb, const float* __restrict__ pos) {
    int row = blockIdx.x;
    int tok = inp[row];
    float mf = (float)mask[row];
    int s = row & (Ss - 1);
    const float* er = emb + (size_t)tok * Dd;
    const float* pr = pos + (size_t)s * Dd;
    float* xr = g_x + (size_t)row * Dd;
    for (int d = threadIdx.x; d < Dd; d += blockDim.x)
        xr[d] = (er[d] + pr[d]) * mf;
}

// ---------------- residual add + LayerNorm (+optional mask mult) --------------
__global__ void ln_residual_kernel(const float* __restrict__ xin, const float* __restrict__ res,
                                   const float* __restrict__ g, const float* __restrict__ beta,
                                   float* __restrict__ outp, const int* __restrict__ mask) {
    __shared__ float red[8];
    int row = blockIdx.x, tid = threadIdx.x;
    const float* xr = xin + (size_t)row * Dd;
    const float* rr = res + (size_t)row * Dd;
    float v0 = xr[tid] + rr[tid];
    float v1 = xr[tid + 256] + rr[tid + 256];

    float s = v0 + v1;
    #pragma unroll
    for (int o = 16; o > 0; o >>= 1) s += __shfl_down_sync(0xffffffffu, s, o);
    if ((tid & 31) == 0) red[tid >> 5] = s;
    __syncthreads();
    if (tid < 8) {
        float t = red[tid];
        #pragma unroll
        for (int o = 4; o > 0; o >>= 1) t += __shfl_down_sync(0xffu, t, o);
        if (tid == 0) red[0] = t;
    }
    __syncthreads();
    float mean = red[0] * (1.f / Dd);
    __syncthreads();

    float d0 = v0 - mean, d1 = v1 - mean;
    float vs = d0 * d0 + d1 * d1;
    #pragma unroll
    for (int o = 16; o > 0; o >>= 1) vs += __shfl_down_sync(0xffffffffu, vs, o);
    if ((tid & 31) == 0) red[tid >> 5] = vs;
    __syncthreads();
    if (tid < 8) {
        float t = red[tid];
        #pragma unroll
        for (int o = 4; o > 0; o >>= 1) t += __shfl_down_sync(0xffu, t, o);
        if (tid == 0) red[0] = t;
    }
    __syncthreads();
    float var = red[0] * (1.f / Dd);
    float inv = rsqrtf(var + 1e-5f);
    float mf = mask ? (float)mask[row] : 1.f;
    outp[(size_t)row * Dd + tid]       = (d0 * inv * g[tid]       + beta[tid])       * mf;
    outp[(size_t)row * Dd + tid + 256] = (d1 * inv * g[tid + 256] + beta[tid + 256]) * mf;
}

// ---------------- masked mean pool over sequence ------------------------------
__global__ void pool_kernel(const int* __restrict__ mask, float* __restrict__ out) {
    __shared__ float red[8];
    int b = blockIdx.x, tid = threadIdx.x;
    float s0 = 0.f, s1 = 0.f;
    for (int t = 0; t < Ss; t++) {
        const float* xr = g_x + ((size_t)(b * Ss + t)) * Dd;
        s0 += xr[tid];
        s1 += xr[tid + 256];
    }
    float c = 0.f;
    for (int t = tid; t < Ss; t += 256) c += (float)mask[b * Ss + t];
    #pragma unroll
    for (int o = 16; o > 0; o >>= 1) c += __shfl_down_sync(0xffffffffu, c, o);
    if ((tid & 31) == 0) red[tid >> 5] = c;
    __syncthreads();
    if (tid < 8) {
        float t2 = red[tid];
        #pragma unroll
        for (int o = 4; o > 0; o >>= 1) t2 += __shfl_down_sync(0xffu, t2, o);
        if (tid == 0) red[0] = t2;
    }
    __syncthreads();
    float div = fmaxf(red[0], 1e-20f);
    out[b * Dd + tid]       = s0 / div;
    out[b * Dd + tid + 256] = s1 / div;
}

// ---------------- host orchestration ------------------------------------------
extern "C" void kernel_launch(void* const* d_in, const int* in_sizes, int n_in,
                              void* d_out, int out_size) {
    (void)in_sizes; (void)n_in; (void)out_size;
    const int*   inp   = (const int*)  d_in[0];
    const int*   mask  = (const int*)  d_in[1];
    const float* emb   = (const float*)d_in[2];
    const float* pos   = (const float*)d_in[3];
    const float* Wq    = (const float*)d_in[4];
    const float* bq    = (const float*)d_in[5];
    const float* Wk    = (const float*)d_in[6];
    const float* bk    = (const float*)d_in[7];
    const float* Wv    = (const float*)d_in[8];
    const float* bv    = (const float*)d_in[9];
    const float* Wo    = (const float*)d_in[10];
    const float* bo    = (const float*)d_in[11];
    const float* ln1g  = (const float*)d_in[12];
    const float* ln1b  = (const float*)d_in[13];
    const float* W1    = (const float*)d_in[14];
    const float* b1    = (const float*)d_in[15];
    const float* W2    = (const float*)d_in[16];
    const float* b2    = (const float*)d_in[17];
    const float* ln2g  = (const float*)d_in[18];
    const float* ln2b  = (const float*)d_in[19];
    float* out = (float*)d_out;

    float *xp, *qp, *kp, *vp, *ap, *pp, *hp;
    __half *xb, *hb, *wb;
    __nv_bfloat16 *qhh, *qll, *khh, *kll, *vhh, *vll;
    cudaGetSymbolAddress((void**)&xp, g_x);
    cudaGetSymbolAddress((void**)&qp, g_q);
    cudaGetSymbolAddress((void**)&kp, g_k);
    cudaGetSymbolAddress((void**)&vp, g_v);
    cudaGetSymbolAddress((void**)&ap, g_attn);
    cudaGetSymbolAddress((void**)&pp, g_proj);
    cudaGetSymbolAddress((void**)&hp, g_h);
    cudaGetSymbolAddress((void**)&xb, g_xb);
    cudaGetSymbolAddress((void**)&hb, g_hb);
    cudaGetSymbolAddress((void**)&wb, g_wb);
    cudaGetSymbolAddress((void**)&qhh, g_qhh);
    cudaGetSymbolAddress((void**)&qll, g_qll);
    cudaGetSymbolAddress((void**)&khh, g_khh);
    cudaGetSymbolAddress((void**)&kll, g_kll);
    cudaGetSymbolAddress((void**)&vhh, g_vhh);
    cudaGetSymbolAddress((void**)&vll, g_vll);

    cudaFuncSetAttribute(gemm_hmma<false>, cudaFuncAttributeMaxDynamicSharedMemorySize, GEMM_SMEM_BYTES);
    cudaFuncSetAttribute(gemm_hmma<true>,  cudaFuncAttributeMaxDynamicSharedMemorySize, GEMM_SMEM_BYTES);
    cudaFuncSetAttribute(attn_mma, cudaFuncAttributeMaxDynamicSharedMemorySize, ATT_SMEM);

    embed_kernel<<<ROWS, 256>>>(inp, mask, emb, pos);

    dim3 gD(Dd / 128, ROWS / 128);
    dim3 gF(FF / 128, ROWS / 128);
    dim3 gA(Ss / 128, BH);
    dim3 gV(Ss / 64, BH);

    const int cvActD = (ROWS * Dd) / 1024;
    const int cvActF = (ROWS * FF) / 1024;
    const int cvWdd  = (Dd * Dd) / 1024;
    const int cvW1   = (FF * Dd) / 1024;
    const int cvW2   = (Dd * FF) / 1024;

    for (int l = 0; l < Ll; l++) {
        const float* Wq_l = Wq + (size_t)l * Dd * Dd;
        const float* Wk_l = Wk + (size_t)l * Dd * Dd;
        const float* Wv_l = Wv + (size_t)l * Dd * Dd;
        const float* Wo_l = Wo + (size_t)l * Dd * Dd;
        const float* W1_l = W1 + (size_t)l * FF * Dd;
        const float* W2_l = W2 + (size_t)l * Dd * FF;
        const float* bq_l = bq + (size_t)l * Dd;
        const float* bk_l = bk + (size_t)l * Dd;
        const float* bv_l = bv + (size_t)l * Dd;
        const float* bo_l = bo + (size_t)l * Dd;
        const float* b1_l = b1 + (size_t)l * FF;
        const float* b2_l = b2 + (size_t)l * Dd;

        // QKV projections (fp16 2-term HMMA)
        conv_split<true><<<cvActD, 256>>>(xp, xb, Dd);
        conv_split<false><<<cvWdd, 256>>>(Wq_l, wb, Dd);
        gemm_hmma<false><<<gD, 256, GEMM_SMEM_BYTES>>>(xb, wb, bq_l, qp, ROWS, Dd, KP1);
        conv_split<false><<<cvWdd, 256>>>(Wk_l, wb, Dd);
        gemm_hmma<false><<<gD, 256, GEMM_SMEM_BYTES>>>(xb, wb, bk_l, kp, ROWS, Dd, KP1);
        conv_split<false><<<cvWdd, 256>>>(Wv_l, wb, Dd);
        gemm_hmma<false><<<gD, 256, GEMM_SMEM_BYTES>>>(xb, wb, bv_l, vp, ROWS, Dd, KP1);

        // head-split conversions + bf16 3-pass HMMA flash attention (R7)
        conv_heads<<<ROWS, 128>>>(qp, qhh, qll);
        conv_heads<<<ROWS, 128>>>(kp, khh, kll);
        conv_vT<<<gV, 256>>>(vp, vhh, vll);
        attn_mma<<<gA, 256, ATT_SMEM>>>(qhh, qll, khh, kll, vhh, vll, mask, ap);

        // output projection
        conv_split<true><<<cvActD, 256>>>(ap, xb, Dd);
        conv_split<false><<<cvWdd, 256>>>(Wo_l, wb, Dd);
        gemm_hmma<false><<<gD, 256, GEMM_SMEM_BYTES>>>(xb, wb, bo_l, pp, ROWS, Dd, KP1);
        ln_residual_kernel<<<ROWS, 256>>>(xp, pp, ln1g + (size_t)l * Dd, ln1b + (size_t)l * Dd,
                                          xp, (const int*)nullptr);

        // FFN
        conv_split<true><<<cvActD, 256>>>(xp, xb, Dd);
        conv_split<false><<<cvW1, 256>>>(W1_l, wb, Dd);
        gemm_hmma<true><<<gF, 256, GEMM_SMEM_BYTES>>>(xb, wb, b1_l, hp, ROWS, FF, KP1);
        conv_split<true><<<cvActF, 256>>>(hp, hb, FF);
        conv_split<false><<<cvW2, 256>>>(W2_l, wb, FF);
        gemm_hmma<false><<<gD, 256, GEMM_SMEM_BYTES>>>(hb, wb, b2_l, pp, ROWS, Dd, KP2);
        ln_residual_kernel<<<ROWS, 256>>>(xp, pp, ln2g + (size_t)l * Dd, ln2b + (size_t)l * Dd,
                                          xp, mask);
    }

    pool_kernel<<<Bb, 256>>>(mask, out);
}

// round 17
// speedup vs baseline: 3.1662x; 1.4225x over previous
#include <cuda_runtime.h>
#include <cuda_fp16.h>
#include <cuda_bf16.h>
#include <math.h>
#include <stdint.h>
#include <string.h>

// Problem constants
#define Bb   16
#define Ss   1024
#define Dd   512
#define Hh   8
#define DH   64
#define Ll   6
#define FF   2048
#define ROWS (Bb*Ss)       // 16384
#define KP1  Dd            // 512   (plain fp16, 1-term)
#define KP2  FF            // 2048
#define BH   (Bb*Hh)       // 128

// ---------------- scratch (device globals; no runtime allocation) -------------
__device__ float g_x[ROWS*Dd];
__device__ float g_q[ROWS*Dd];
__device__ float g_k[ROWS*Dd];
__device__ float g_v[ROWS*Dd];
__device__ float g_attn[ROWS*Dd];
__device__ float g_proj[ROWS*Dd];
__device__ float g_h[ROWS*FF];
__device__ __half g_xb[(size_t)ROWS*KP1];   // 16 MB  fp16 activations
__device__ __half g_hb[(size_t)ROWS*KP2];   // 64 MB  fp16 FFN hidden
__device__ __half g_wb[(size_t)FF*KP1];     // 2 MB   fp16 weight staging
// per-head split-bf16 Q/K [BH,S,64] and V transposed [BH,64,S]  (R7-validated)
__device__ __nv_bfloat16 g_qhh[(size_t)BH*Ss*64];
__device__ __nv_bfloat16 g_qll[(size_t)BH*Ss*64];
__device__ __nv_bfloat16 g_khh[(size_t)BH*Ss*64];
__device__ __nv_bfloat16 g_kll[(size_t)BH*Ss*64];
__device__ __nv_bfloat16 g_vhh[(size_t)BH*Ss*64];
__device__ __nv_bfloat16 g_vll[(size_t)BH*Ss*64];

// ======================= PTX helpers (portable, sm_80+) =======================
__device__ __forceinline__ uint32_t smem_u32(const void* p) {
    uint32_t a;
    asm("{ .reg .u64 t; cvta.to.shared.u64 t, %1; cvt.u32.u64 %0, t; }" : "=r"(a) : "l"(p));
    return a;
}
#define CP_ASYNC16(dst, src) \
    asm volatile("cp.async.cg.shared.global [%0], [%1], 16;" :: "r"(dst), "l"(src) : "memory")
#define CP_COMMIT() asm volatile("cp.async.commit_group;" ::: "memory")
#define CP_WAIT(n)  asm volatile("cp.async.wait_group %0;" :: "n"(n) : "memory")

#define SWZ128(o) ((o) ^ (((o) >> 3) & 0x70))

__device__ __forceinline__ void ldmatrix_x4(uint32_t& r0, uint32_t& r1, uint32_t& r2, uint32_t& r3,
                                            uint32_t addr) {
    asm volatile("ldmatrix.sync.aligned.m8n8.x4.shared.b16 {%0,%1,%2,%3}, [%4];"
                 : "=r"(r0), "=r"(r1), "=r"(r2), "=r"(r3) : "r"(addr));
}
// fp16 MMA (GEMM path)
__device__ __forceinline__ void mma_f16(float& c0, float& c1, float& c2, float& c3,
                                        uint32_t a0, uint32_t a1, uint32_t a2, uint32_t a3,
                                        uint32_t b0, uint32_t b1) {
    asm volatile("mma.sync.aligned.m16n8k16.row.col.f32.f16.f16.f32 "
                 "{%0,%1,%2,%3}, {%4,%5,%6,%7}, {%8,%9}, {%10,%11,%12,%13};"
                 : "=f"(c0), "=f"(c1), "=f"(c2), "=f"(c3)
                 : "r"(a0), "r"(a1), "r"(a2), "r"(a3), "r"(b0), "r"(b1),
                   "f"(c0), "f"(c1), "f"(c2), "f"(c3));
}
// bf16 MMA (attention path, R7-validated)
__device__ __forceinline__ void mma_bf16(float& c0, float& c1, float& c2, float& c3,
                                         uint32_t a0, uint32_t a1, uint32_t a2, uint32_t a3,
                                         uint32_t b0, uint32_t b1) {
    asm volatile("mma.sync.aligned.m16n8k16.row.col.f32.bf16.bf16.f32 "
                 "{%0,%1,%2,%3}, {%4,%5,%6,%7}, {%8,%9}, {%10,%11,%12,%13};"
                 : "=f"(c0), "=f"(c1), "=f"(c2), "=f"(c3)
                 : "r"(a0), "r"(a1), "r"(a2), "r"(a3), "r"(b0), "r"(b1),
                   "f"(c0), "f"(c1), "f"(c2), "f"(c3));
}

// ldmatrix x4 address for a 16x16 block inside a [rows x 128B] SW128 tile (R7).
__device__ __forceinline__ uint32_t ldsm_addr(uint32_t tilebase, int base16, int kk) {
    int lane = threadIdx.x & 31;
    int g = lane >> 3, r8 = lane & 7;
    int r = base16 + (g & 1) * 8 + r8;
    int bc = kk * 32 + (g >> 1) * 16;
    return tilebase + (uint32_t)(r * 128 + (bc ^ ((r & 7) * 16)));
}

// ================= fp32 -> fp16 conversion (1-term) ===========================
__global__ void conv_fp16(const float* __restrict__ src, __half* __restrict__ dst) {
    size_t lin = ((size_t)blockIdx.x * 256 + threadIdx.x) * 4;
    float4 v = *(const float4*)(src + lin);
    __half2 a = __halves2half2(__float2half(v.x), __float2half(v.y));
    __half2 b = __halves2half2(__float2half(v.z), __float2half(v.w));
    uint32_t p0, p1;
    memcpy(&p0, &a, 4); memcpy(&p1, &b, 4);
    *(uint2*)(dst + lin) = make_uint2(p0, p1);
}

// ============ attention head-split conversions (bf16, R7-validated) ===========
__global__ void conv_heads(const float* __restrict__ src,
                           __nv_bfloat16* __restrict__ hi, __nv_bfloat16* __restrict__ lo) {
    int row = blockIdx.x, tid = threadIdx.x;       // 128 threads
    int d = tid * 4;
    float4 v = *(const float4*)(src + (size_t)row * Dd + d);
    int b = row >> 10, s = row & 1023, h = d >> 6, dl = d & 63;
    size_t ob = ((size_t)(b * Hh + h) * Ss + s) * 64 + dl;
    float vv[4] = {v.x, v.y, v.z, v.w};
    __nv_bfloat16 hh[4], ll[4];
    #pragma unroll
    for (int i = 0; i < 4; i++) {
        hh[i] = __float2bfloat16(vv[i]);
        ll[i] = __float2bfloat16(vv[i] - __bfloat162float(hh[i]));
    }
    uint32_t a0, a1, b0, b1;
    { __nv_bfloat162 t0(hh[0], hh[1]), t1(hh[2], hh[3]), t2(ll[0], ll[1]), t3(ll[2], ll[3]);
      memcpy(&a0, &t0, 4); memcpy(&a1, &t1, 4); memcpy(&b0, &t2, 4); memcpy(&b1, &t3, 4); }
    *(uint2*)(hi + ob) = make_uint2(a0, a1);
    *(uint2*)(lo + ob) = make_uint2(b0, b1);
}

__global__ void conv_vT(const float* __restrict__ src,
                        __nv_bfloat16* __restrict__ hi, __nv_bfloat16* __restrict__ lo) {
    __shared__ float tile[64][65];
    int s0 = blockIdx.x * 64, bh = blockIdx.y;
    int b = bh >> 3, h = bh & 7;
    int tid = threadIdx.x;                          // 256 threads
    for (int p = tid; p < 1024; p += 256) {
        int r = p >> 4, c4 = (p & 15) * 4;
        float4 v = *(const float4*)(src + ((size_t)(b * Ss + s0 + r)) * Dd + h * 64 + c4);
        tile[r][c4 + 0] = v.x; tile[r][c4 + 1] = v.y;
        tile[r][c4 + 2] = v.z; tile[r][c4 + 3] = v.w;
    }
    __syncthreads();
    for (int p = tid; p < 2048; p += 256) {
        int dd = p >> 5, sc = (p & 31) * 2;
        float v0 = tile[sc][dd], v1 = tile[sc + 1][dd];
        __nv_bfloat16 h0 = __float2bfloat16(v0), h1 = __float2bfloat16(v1);
        __nv_bfloat16 l0 = __float2bfloat16(v0 - __bfloat162float(h0));
        __nv_bfloat16 l1 = __float2bfloat16(v1 - __bfloat162float(h1));
        uint32_t ph, pl;
        { __nv_bfloat162 th(h0, h1), tl(l0, l1); memcpy(&ph, &th, 4); memcpy(&pl, &tl, 4); }
        size_t ob = ((size_t)bh * 64 + dd) * Ss + s0 + sc;
        *(uint32_t*)(hi + ob) = ph;
        *(uint32_t*)(lo + ob) = pl;
    }
}

// ================= HMMA GEMM (fp16, R12 mainloop — unchanged) =================
#define GEMM_SMEM_BYTES (4 * 16384)
template <bool RELU>
__global__ void __launch_bounds__(256, 2) gemm_hmma(
    const __half* __restrict__ A, const __half* __restrict__ W,
    const float* __restrict__ bias, float* __restrict__ C, int M, int N, int Kp) {
    extern __shared__ char smem[];
    const uint32_t sb = smem_u32(smem);
    const int tid = threadIdx.x;
    const int lane = tid & 31, wid = tid >> 5;
    const int wm = wid & 1, wn = wid >> 1;
    const int m0 = blockIdx.y * 128, n0 = blockIdx.x * 128;

    const uint32_t offA[2] = {0u, 32768u};
    const uint32_t offB[2] = {16384u, 49152u};

    const __half* Ap = A + (size_t)m0 * Kp;
    const __half* Bp = W + (size_t)n0 * Kp;
    const int nc = Kp >> 6;

    const int lrow = tid >> 1;
    const int lch0 = (tid & 1) * 4;

    float acc[4][4][4];
    #pragma unroll
    for (int i = 0; i < 4; i++)
        #pragma unroll
        for (int j = 0; j < 4; j++)
            #pragma unroll
            for (int r = 0; r < 4; r++) acc[i][j][r] = 0.f;

    auto issue = [&](int i, int b) {
        const __half* Ac = Ap + (size_t)i * 64;
        const __half* Bc = Bp + (size_t)i * 64;
        #pragma unroll
        for (int j = 0; j < 4; j++) {
            int ch = lch0 + j;
            uint32_t so = SWZ128((uint32_t)(lrow * 128 + ch * 16));
            CP_ASYNC16(sb + offA[b] + so, Ac + (size_t)lrow * Kp + ch * 8);
            CP_ASYNC16(sb + offB[b] + so, Bc + (size_t)lrow * Kp + ch * 8);
        }
    };

    issue(0, 0); CP_COMMIT();

    for (int i = 0; i < nc; i++) {
        int b = i & 1;
        if (i + 1 < nc) { issue(i + 1, b ^ 1); CP_COMMIT(); CP_WAIT(1); }
        else            { CP_WAIT(0); }
        __syncthreads();

        const uint32_t baA = sb + offA[b];
        const uint32_t baB = sb + offB[b];
        #pragma unroll
        for (int kk = 0; kk < 4; kk++) {
            uint32_t a[4][4];
            {
                int r = lane & 15, half = lane >> 4;
                #pragma unroll
                for (int mi = 0; mi < 4; mi++) {
                    int row = wm * 64 + mi * 16 + r;
                    uint32_t off = (uint32_t)(row * 128)
                                 + (uint32_t)((kk * 32 + half * 16) ^ ((row & 7) * 16));
                    ldmatrix_x4(a[mi][0], a[mi][1], a[mi][2], a[mi][3], baA + off);
                }
            }
            uint32_t bfr[4][2];
            {
                int g = lane >> 3, r8 = lane & 7;
                #pragma unroll
                for (int p = 0; p < 2; p++) {
                    int row = wn * 32 + p * 16 + (g & 1) * 8 + r8;
                    uint32_t off = (uint32_t)(row * 128)
                                 + (uint32_t)((kk * 32 + (g >> 1) * 16) ^ ((row & 7) * 16));
                    uint32_t r0, r1, r2, r3;
                    ldmatrix_x4(r0, r1, r2, r3, baB + off);
                    bfr[p * 2 + 0][0] = r0; bfr[p * 2 + 0][1] = r2;
                    bfr[p * 2 + 1][0] = r1; bfr[p * 2 + 1][1] = r3;
                }
            }
            #pragma unroll
            for (int mi = 0; mi < 4; mi++)
                #pragma unroll
                for (int ni = 0; ni < 4; ni++)
                    mma_f16(acc[mi][ni][0], acc[mi][ni][1], acc[mi][ni][2], acc[mi][ni][3],
                            a[mi][0], a[mi][1], a[mi][2], a[mi][3],
                            bfr[ni][0], bfr[ni][1]);
        }
        __syncthreads();
    }

    #pragma unroll
    for (int mi = 0; mi < 4; mi++) {
        int row0 = m0 + wm * 64 + mi * 16 + (lane >> 2);
        #pragma unroll
        for (int ni = 0; ni < 4; ni++) {
            int col = n0 + wn * 32 + ni * 8 + (lane & 3) * 2;
            float b0 = bias[col], b1 = bias[col + 1];
            float2 v0 = make_float2(acc[mi][ni][0] + b0, acc[mi][ni][1] + b1);
            float2 v1 = make_float2(acc[mi][ni][2] + b0, acc[mi][ni][3] + b1);
            if (RELU) {
                v0.x = fmaxf(v0.x, 0.f); v0.y = fmaxf(v0.y, 0.f);
                v1.x = fmaxf(v1.x, 0.f); v1.y = fmaxf(v1.y, 0.f);
            }
            *(float2*)(C + (size_t)row0 * N + col)       = v0;
            *(float2*)(C + (size_t)(row0 + 8) * N + col) = v1;
        }
    }
}

// ========= HMMA flash attention (split-bf16, 3-pass — R7-validated) ===========
#define A_QH   0
#define A_QL   16384
#define A_KV   32768
#define A_MSK  98304
#define ATT_SMEM (98304 + 512)

__global__ void __launch_bounds__(256) attn_mma(
    const __nv_bfloat16* __restrict__ qh_, const __nv_bfloat16* __restrict__ ql_,
    const __nv_bfloat16* __restrict__ kh_, const __nv_bfloat16* __restrict__ kl_,
    const __nv_bfloat16* __restrict__ vh_, const __nv_bfloat16* __restrict__ vl_,
    const int* __restrict__ mask, float* __restrict__ out) {
    extern __shared__ char smem[];
    const uint32_t sb = smem_u32(smem);
    const int tid = threadIdx.x, lane = tid & 31, w = tid >> 5;
    const int bh = blockIdx.y, b = bh >> 3, h = bh & 7;
    const int q0 = blockIdx.x * 128;
    const int R0 = w * 16;

    const __nv_bfloat16* qsrc[2] = {qh_ + (size_t)bh * Ss * 64, ql_ + (size_t)bh * Ss * 64};
    const __nv_bfloat16* ksrc[2] = {kh_ + (size_t)bh * Ss * 64, kl_ + (size_t)bh * Ss * 64};
    const __nv_bfloat16* vsrc[2] = {vh_ + (size_t)bh * 64 * Ss, vl_ + (size_t)bh * 64 * Ss};

    auto issue_kv = [&](int t, int buf) {
        int k0 = t * 64;
        uint32_t dbase = sb + A_KV + buf * 32768;
        #pragma unroll
        for (int j = 0; j < 8; j++) {
            int c = j * 256 + tid;
            int tn = c >> 9, wv = c & 511;
            int r = wv >> 3, ch = wv & 7;
            uint32_t dst = dbase + tn * 8192 + SWZ128((uint32_t)(r * 128 + ch * 16));
            const __nv_bfloat16* src;
            if (tn == 0)      src = ksrc[0] + (size_t)(k0 + r) * 64 + ch * 8;
            else if (tn == 1) src = ksrc[1] + (size_t)(k0 + r) * 64 + ch * 8;
            else if (tn == 2) src = vsrc[0] + (size_t)r * Ss + k0 + ch * 8;
            else              src = vsrc[1] + (size_t)r * Ss + k0 + ch * 8;
            CP_ASYNC16(dst, src);
        }
        if (tid < 64) {
            float* smM = (float*)(smem + A_MSK + buf * 256);
            smM[tid] = mask[b * Ss + k0 + tid] ? 0.f : -1e20f;
        }
    };

    #pragma unroll
    for (int j = 0; j < 8; j++) {
        int c = j * 256 + tid;
        int tn = c >> 10, wv = c & 1023;
        int r = wv >> 3, ch = wv & 7;
        uint32_t dst = sb + (tn ? A_QL : A_QH) + SWZ128((uint32_t)(r * 128 + ch * 16));
        CP_ASYNC16(dst, qsrc[tn] + (size_t)(q0 + r) * 64 + ch * 8);
    }
    issue_kv(0, 0);
    CP_COMMIT();

    uint32_t qhf[4][4], qlf[4][4];
    float oacc[8][4];
    #pragma unroll
    for (int j = 0; j < 8; j++)
        #pragma unroll
        for (int r = 0; r < 4; r++) oacc[j][r] = 0.f;
    float m0 = -INFINITY, m1 = -INFINITY, l0 = 0.f, l1 = 0.f;

    for (int t = 0; t < 16; t++) {
        int buf = t & 1;
        if (t < 15) { issue_kv(t + 1, buf ^ 1); CP_COMMIT(); CP_WAIT(1); }
        else        { CP_WAIT(0); }
        __syncthreads();

        if (t == 0) {
            #pragma unroll
            for (int kk = 0; kk < 4; kk++) {
                ldmatrix_x4(qhf[kk][0], qhf[kk][1], qhf[kk][2], qhf[kk][3],
                            ldsm_addr(sb + A_QH, R0, kk));
                ldmatrix_x4(qlf[kk][0], qlf[kk][1], qlf[kk][2], qlf[kk][3],
                            ldsm_addr(sb + A_QL, R0, kk));
            }
        }

        const uint32_t bKH = sb + A_KV + buf * 32768;
        const uint32_t bKL = bKH + 8192;
        const uint32_t bVH = bKH + 16384;
        const uint32_t bVL = bKH + 24576;
        const float* smM = (const float*)(smem + A_MSK + buf * 256);

        float sacc[8][4];
        #pragma unroll
        for (int j = 0; j < 8; j++)
            #pragma unroll
            for (int r = 0; r < 4; r++) sacc[j][r] = 0.f;

        #pragma unroll
        for (int kk = 0; kk < 4; kk++) {
            uint32_t kb[8][2];
            #pragma unroll
            for (int nt = 0; nt < 4; nt++) {
                uint32_t r0, r1, r2, r3;
                ldmatrix_x4(r0, r1, r2, r3, ldsm_addr(bKH, nt * 16, kk));
                kb[nt * 2 + 0][0] = r0; kb[nt * 2 + 0][1] = r2;
                kb[nt * 2 + 1][0] = r1; kb[nt * 2 + 1][1] = r3;
            }
            #pragma unroll
            for (int j = 0; j < 8; j++)
                mma_bf16(sacc[j][0], sacc[j][1], sacc[j][2], sacc[j][3],
                         qhf[kk][0], qhf[kk][1], qhf[kk][2], qhf[kk][3], kb[j][0], kb[j][1]);
            #pragma unroll
            for (int j = 0; j < 8; j++)
                mma_bf16(sacc[j][0], sacc[j][1], sacc[j][2], sacc[j][3],
                         qlf[kk][0], qlf[kk][1], qlf[kk][2], qlf[kk][3], kb[j][0], kb[j][1]);
            #pragma unroll
            for (int nt = 0; nt < 4; nt++) {
                uint32_t r0, r1, r2, r3;
                ldmatrix_x4(r0, r1, r2, r3, ldsm_addr(bKL, nt * 16, kk));
                kb[nt * 2 + 0][0] = r0; kb[nt * 2 + 0][1] = r2;
                kb[nt * 2 + 1][0] = r1; kb[nt * 2 + 1][1] = r3;
            }
            #pragma unroll
            for (int j = 0; j < 8; j++)
                mma_bf16(sacc[j][0], sacc[j][1], sacc[j][2], sacc[j][3],
                         qhf[kk][0], qhf[kk][1], qhf[kk][2], qhf[kk][3], kb[j][0], kb[j][1]);
        }

        float mt0 = -INFINITY, mt1 = -INFINITY;
        #pragma unroll
        for (int j = 0; j < 8; j++) {
            int c0 = j * 8 + (lane & 3) * 2;
            float mk0 = smM[c0], mk1 = smM[c0 + 1];
            sacc[j][0] = (sacc[j][0] + mk0) * 0.125f;
            sacc[j][1] = (sacc[j][1] + mk1) * 0.125f;
            sacc[j][2] = (sacc[j][2] + mk0) * 0.125f;
            sacc[j][3] = (sacc[j][3] + mk1) * 0.125f;
            mt0 = fmaxf(mt0, fmaxf(sacc[j][0], sacc[j][1]));
            mt1 = fmaxf(mt1, fmaxf(sacc[j][2], sacc[j][3]));
        }
        mt0 = fmaxf(mt0, __shfl_xor_sync(0xffffffffu, mt0, 1));
        mt0 = fmaxf(mt0, __shfl_xor_sync(0xffffffffu, mt0, 2));
        mt1 = fmaxf(mt1, __shfl_xor_sync(0xffffffffu, mt1, 1));
        mt1 = fmaxf(mt1, __shfl_xor_sync(0xffffffffu, mt1, 2));

        float mn0 = fmaxf(m0, mt0), mn1 = fmaxf(m1, mt1);
        float sc0 = __expf(m0 - mn0), sc1 = __expf(m1 - mn1);

        uint32_t phi[4][4], plo[4][4];
        float ps0 = 0.f, ps1 = 0.f;
        #pragma unroll
        for (int j = 0; j < 8; j++) {
            float p0 = __expf(sacc[j][0] - mn0);
            float p1 = __expf(sacc[j][1] - mn0);
            float p2 = __expf(sacc[j][2] - mn1);
            float p3 = __expf(sacc[j][3] - mn1);
            ps0 += p0 + p1; ps1 += p2 + p3;
            __nv_bfloat16 h0 = __float2bfloat16(p0), h1 = __float2bfloat16(p1);
            __nv_bfloat16 h2 = __float2bfloat16(p2), h3 = __float2bfloat16(p3);
            uint32_t H01, H23, L01, L23;
            { __nv_bfloat162 a(h0, h1), c(h2, h3);
              __nv_bfloat162 e(__float2bfloat16(p0 - __bfloat162float(h0)),
                               __float2bfloat16(p1 - __bfloat162float(h1)));
              __nv_bfloat162 f(__float2bfloat16(p2 - __bfloat162float(h2)),
                               __float2bfloat16(p3 - __bfloat162float(h3)));
              memcpy(&H01, &a, 4); memcpy(&H23, &c, 4);
              memcpy(&L01, &e, 4); memcpy(&L23, &f, 4); }
            int kk = j >> 1, o = (j & 1) * 2;
            phi[kk][o + 0] = H01; phi[kk][o + 1] = H23;
            plo[kk][o + 0] = L01; plo[kk][o + 1] = L23;
        }
        ps0 += __shfl_xor_sync(0xffffffffu, ps0, 1);
        ps0 += __shfl_xor_sync(0xffffffffu, ps0, 2);
        ps1 += __shfl_xor_sync(0xffffffffu, ps1, 1);
        ps1 += __shfl_xor_sync(0xffffffffu, ps1, 2);
        l0 = l0 * sc0 + ps0; l1 = l1 * sc1 + ps1;
        m0 = mn0; m1 = mn1;

        #pragma unroll
        for (int j = 0; j < 8; j++) {
            oacc[j][0] *= sc0; oacc[j][1] *= sc0;
            oacc[j][2] *= sc1; oacc[j][3] *= sc1;
        }

        #pragma unroll
        for (int kk = 0; kk < 4; kk++) {
            uint32_t vb[8][2];
            #pragma unroll
            for (int nt = 0; nt < 4; nt++) {
                uint32_t r0, r1, r2, r3;
                ldmatrix_x4(r0, r1, r2, r3, ldsm_addr(bVH, nt * 16, kk));
                vb[nt * 2 + 0][0] = r0; vb[nt * 2 + 0][1] = r2;
                vb[nt * 2 + 1][0] = r1; vb[nt * 2 + 1][1] = r3;
            }
            #pragma unroll
            for (int j = 0; j < 8; j++)
                mma_bf16(oacc[j][0], oacc[j][1], oacc[j][2], oacc[j][3],
                         phi[kk][0], phi[kk][1], phi[kk][2], phi[kk][3], vb[j][0], vb[j][1]);
            #pragma unroll
            for (int j = 0; j < 8; j++)
                mma_bf16(oacc[j][0], oacc[j][1], oacc[j][2], oacc[j][3],
                         plo[kk][0], plo[kk][1], plo[kk][2], plo[kk][3], vb[j][0], vb[j][1]);
            #pragma unroll
            for (int nt = 0; nt < 4; nt++) {
                uint32_t r0, r1, r2, r3;
                ldmatrix_x4(r0, r1, r2, r3, ldsm_addr(bVL, nt * 16, kk));
                vb[nt * 2 + 0][0] = r0; vb[nt * 2 + 0][1] = r2;
                vb[nt * 2 + 1][0] = r1; vb[nt * 2 + 1][1] = r3;
            }
            #pragma unroll
            for (int j = 0; j < 8; j++)
                mma_bf16(oacc[j][0], oacc[j][1], oacc[j][2], oacc[j][3],
                         phi[kk][0], phi[kk][1], phi[kk][2], phi[kk][3], vb[j][0], vb[j][1]);
        }
        __syncthreads();
    }

    float inv0 = 1.f / l0, inv1 = 1.f / l1;
    int row0 = q0 + R0 + (lane >> 2);
    #pragma unroll
    for (int j = 0; j < 8; j++) {
        int col = h * 64 + j * 8 + (lane & 3) * 2;
        *(float2*)(out + ((size_t)(b * Ss + row0)) * Dd + col) =
            make_float2(oacc[j][0] * inv0, oacc[j][1] * inv0);
        *(float2*)(out + ((size_t)(b * Ss + row0 + 8)) * Dd + col) =
            make_float2(oacc[j][2] * inv1, oacc[j][3] * inv1);
    }
}

// ---------------- embedding + positional + mask -------------------------------
__global__ void embed_kernel(const int* __restrict__ inp, const int* __restrict__ mask,
                             const float* __restrict__ emb, const float* __restrict__ pos) {
    int row = blockIdx.x;
    int tok = inp[row];
    float mf = (float)mask[row];
    int s = row & (Ss - 1);
    const float* er = emb + (size_t)tok * Dd;
    const float* pr = pos + (size_t)s * Dd;
    float* xr = g_x + (size_t)row * Dd;
    for (int d = threadIdx.x; d < Dd; d += blockDim.x)
        xr[d] = (er[d] + pr[d]) * mf;
}

// ---------------- residual add + LayerNorm (+optional mask mult) --------------
__global__ void ln_residual_kernel(const float* __restrict__ xin, const float* __restrict__ res,
                                   const float* __restrict__ g, const float* __restrict__ beta,
                                   float* __restrict__ outp, const int* __restrict__ mask) {
    __shared__ float red[8];
    int row = blockIdx.x, tid = threadIdx.x;
    const float* xr = xin + (size_t)row * Dd;
    const float* rr = res + (size_t)row * Dd;
    float v0 = xr[tid] + rr[tid];
    float v1 = xr[tid + 256] + rr[tid + 256];

    float s = v0 + v1;
    #pragma unroll
    for (int o = 16; o > 0; o >>= 1) s += __shfl_down_sync(0xffffffffu, s, o);
    if ((tid & 31) == 0) red[tid >> 5] = s;
    __syncthreads();
    if (tid < 8) {
        float t = red[tid];
        #pragma unroll
        for (int o = 4; o > 0; o >>= 1) t += __shfl_down_sync(0xffu, t, o);
        if (tid == 0) red[0] = t;
    }
    __syncthreads();
    float mean = red[0] * (1.f / Dd);
    __syncthreads();

    float d0 = v0 - mean, d1 = v1 - mean;
    float vs = d0 * d0 + d1 * d1;
    #pragma unroll
    for (int o = 16; o > 0; o >>= 1) vs += __shfl_down_sync(0xffffffffu, vs, o);
    if ((tid & 31) == 0) red[tid >> 5] = vs;
    __syncthreads();
    if (tid < 8) {
        float t = red[tid];
        #pragma unroll
        for (int o = 4; o > 0; o >>= 1) t += __shfl_down_sync(0xffu, t, o);
        if (tid == 0) red[0] = t;
    }
    __syncthreads();
    float var = red[0] * (1.f / Dd);
    float inv = rsqrtf(var + 1e-5f);
    float mf = mask ? (float)mask[row] : 1.f;
    outp[(size_t)row * Dd + tid]       = (d0 * inv * g[tid]       + beta[tid])       * mf;
    outp[(size_t)row * Dd + tid + 256] = (d1 * inv * g[tid + 256] + beta[tid + 256]) * mf;
}

// ---------------- masked mean pool over sequence ------------------------------
__global__ void pool_kernel(const int* __restrict__ mask, float* __restrict__ out) {
    __shared__ float red[8];
    int b = blockIdx.x, tid = threadIdx.x;
    float s0 = 0.f, s1 = 0.f;
    for (int t = 0; t < Ss; t++) {
        const float* xr = g_x + ((size_t)(b * Ss + t)) * Dd;
        s0 += xr[tid];
        s1 += xr[tid + 256];
    }
    float c = 0.f;
    for (int t = tid; t < Ss; t += 256) c += (float)mask[b * Ss + t];
    #pragma unroll
    for (int o = 16; o > 0; o >>= 1) c += __shfl_down_sync(0xffffffffu, c, o);
    if ((tid & 31) == 0) red[tid >> 5] = c;
    __syncthreads();
    if (tid < 8) {
        float t2 = red[tid];
        #pragma unroll
        for (int o = 4; o > 0; o >>= 1) t2 += __shfl_down_sync(0xffu, t2, o);
        if (tid == 0) red[0] = t2;
    }
    __syncthreads();
    float div = fmaxf(red[0], 1e-20f);
    out[b * Dd + tid]       = s0 / div;
    out[b * Dd + tid + 256] = s1 / div;
}

// ---------------- host orchestration ------------------------------------------
extern "C" void kernel_launch(void* const* d_in, const int* in_sizes, int n_in,
                              void* d_out, int out_size) {
    (void)in_sizes; (void)n_in; (void)out_size;
    const int*   inp   = (const int*)  d_in[0];
    const int*   mask  = (const int*)  d_in[1];
    const float* emb   = (const float*)d_in[2];
    const float* pos   = (const float*)d_in[3];
    const float* Wq    = (const float*)d_in[4];
    const float* bq    = (const float*)d_in[5];
    const float* Wk    = (const float*)d_in[6];
    const float* bk    = (const float*)d_in[7];
    const float* Wv    = (const float*)d_in[8];
    const float* bv    = (const float*)d_in[9];
    const float* Wo    = (const float*)d_in[10];
    const float* bo    = (const float*)d_in[11];
    const float* ln1g  = (const float*)d_in[12];
    const float* ln1b  = (const float*)d_in[13];
    const float* W1    = (const float*)d_in[14];
    const float* b1    = (const float*)d_in[15];
    const float* W2    = (const float*)d_in[16];
    const float* b2    = (const float*)d_in[17];
    const float* ln2g  = (const float*)d_in[18];
    const float* ln2b  = (const float*)d_in[19];
    float* out = (float*)d_out;

    float *xp, *qp, *kp, *vp, *ap, *pp, *hp;
    __half *xb, *hb, *wb;
    __nv_bfloat16 *qhh, *qll, *khh, *kll, *vhh, *vll;
    cudaGetSymbolAddress((void**)&xp, g_x);
    cudaGetSymbolAddress((void**)&qp, g_q);
    cudaGetSymbolAddress((void**)&kp, g_k);
    cudaGetSymbolAddress((void**)&vp, g_v);
    cudaGetSymbolAddress((void**)&ap, g_attn);
    cudaGetSymbolAddress((void**)&pp, g_proj);
    cudaGetSymbolAddress((void**)&hp, g_h);
    cudaGetSymbolAddress((void**)&xb, g_xb);
    cudaGetSymbolAddress((void**)&hb, g_hb);
    cudaGetSymbolAddress((void**)&wb, g_wb);
    cudaGetSymbolAddress((void**)&qhh, g_qhh);
    cudaGetSymbolAddress((void**)&qll, g_qll);
    cudaGetSymbolAddress((void**)&khh, g_khh);
    cudaGetSymbolAddress((void**)&kll, g_kll);
    cudaGetSymbolAddress((void**)&vhh, g_vhh);
    cudaGetSymbolAddress((void**)&vll, g_vll);

    cudaFuncSetAttribute(gemm_hmma<false>, cudaFuncAttributeMaxDynamicSharedMemorySize, GEMM_SMEM_BYTES);
    cudaFuncSetAttribute(gemm_hmma<true>,  cudaFuncAttributeMaxDynamicSharedMemorySize, GEMM_SMEM_BYTES);
    cudaFuncSetAttribute(attn_mma, cudaFuncAttributeMaxDynamicSharedMemorySize, ATT_SMEM);

    embed_kernel<<<ROWS, 256>>>(inp, mask, emb, pos);

    dim3 gD(Dd / 128, ROWS / 128);
    dim3 gF(FF / 128, ROWS / 128);
    dim3 gA(Ss / 128, BH);
    dim3 gV(Ss / 64, BH);

    const int cvActD = (ROWS * Dd) / 1024;   // fp32->fp16 activations [ROWS,Dd]
    const int cvActF = (ROWS * FF) / 1024;
    const int cvWdd  = (Dd * Dd) / 1024;
    const int cvW1   = (FF * Dd) / 1024;
    const int cvW2   = (Dd * FF) / 1024;

    for (int l = 0; l < Ll; l++) {
        const float* Wq_l = Wq + (size_t)l * Dd * Dd;
        const float* Wk_l = Wk + (size_t)l * Dd * Dd;
        const float* Wv_l = Wv + (size_t)l * Dd * Dd;
        const float* Wo_l = Wo + (size_t)l * Dd * Dd;
        const float* W1_l = W1 + (size_t)l * FF * Dd;
        const float* W2_l = W2 + (size_t)l * Dd * FF;
        const float* bq_l = bq + (size_t)l * Dd;
        const float* bk_l = bk + (size_t)l * Dd;
        const float* bv_l = bv + (size_t)l * Dd;
        const float* bo_l = bo + (size_t)l * Dd;
        const float* b1_l = b1 + (size_t)l * FF;
        const float* b2_l = b2 + (size_t)l * Dd;

        // QKV projections (plain fp16 HMMA, K'=512)
        conv_fp16<<<cvActD, 256>>>(xp, xb);
        conv_fp16<<<cvWdd, 256>>>(Wq_l, wb);
        gemm_hmma<false><<<gD, 256, GEMM_SMEM_BYTES>>>(xb, wb, bq_l, qp, ROWS, Dd, KP1);
        conv_fp16<<<cvWdd, 256>>>(Wk_l, wb);
        gemm_hmma<false><<<gD, 256, GEMM_SMEM_BYTES>>>(xb, wb, bk_l, kp, ROWS, Dd, KP1);
        conv_fp16<<<cvWdd, 256>>>(Wv_l, wb);
        gemm_hmma<false><<<gD, 256, GEMM_SMEM_BYTES>>>(xb, wb, bv_l, vp, ROWS, Dd, KP1);

        // head-split conversions + bf16 3-pass HMMA flash attention (R7)
        conv_heads<<<ROWS, 128>>>(qp, qhh, qll);
        conv_heads<<<ROWS, 128>>>(kp, khh, kll);
        conv_vT<<<gV, 256>>>(vp, vhh, vll);
        attn_mma<<<gA, 256, ATT_SMEM>>>(qhh, qll, khh, kll, vhh, vll, mask, ap);

        // output projection
        conv_fp16<<<cvActD, 256>>>(ap, xb);
        conv_fp16<<<cvWdd, 256>>>(Wo_l, wb);
        gemm_hmma<false><<<gD, 256, GEMM_SMEM_BYTES>>>(xb, wb, bo_l, pp, ROWS, Dd, KP1);
        ln_residual_kernel<<<ROWS, 256>>>(xp, pp, ln1g + (size_t)l * Dd, ln1b + (size_t)l * Dd,
                                          xp, (const int*)nullptr);

        // FFN (plain fp16, K'=512 then K'=2048)
        conv_fp16<<<cvActD, 256>>>(xp, xb);
        conv_fp16<<<cvW1, 256>>>(W1_l, wb);
        gemm_hmma<true><<<gF, 256, GEMM_SMEM_BYTES>>>(xb, wb, b1_l, hp, ROWS, FF, KP1);
        conv_fp16<<<cvActF, 256>>>(hp, hb);
        conv_fp16<<<cvW2, 256>>>(W2_l, wb);
        gemm_hmma<false><<<gD, 256, GEMM_SMEM_BYTES>>>(hb, wb, b2_l, pp, ROWS, Dd, KP2);
        ln_residual_kernel<<<ROWS, 256>>>(xp, pp, ln2g + (size_t)l * Dd, ln2b + (size_t)l * Dd,
                                          xp, mask);
    }

    pool_kernel<<<Bb, 256>>>(mask, out);
}